// round 1
// baseline (speedup 1.0000x reference)
#include <cuda_runtime.h>
#include <cstdint>

#define DD      128
#define NNODES  40000
#define NEDGES  640000

using u64 = unsigned long long;

// Scratch (sanctioned: __device__ globals, no allocation)
__device__ float g_P[NNODES * DD];    // nodes @ mw1_top + mb1
__device__ float g_agg[NNODES * DD];  // scatter-add destination
__device__ float g_H[NNODES * DD];    // hidden of update MLP

// ---------------------------------------------------------------------------
// f32x2 packed-FMA helpers (sm_100a: FFMA2 is 2x the scalar FFMA rate)
// ---------------------------------------------------------------------------
__device__ __forceinline__ u64 pk2(float lo, float hi) {
    u64 r; asm("mov.b64 %0, {%1, %2};" : "=l"(r) : "f"(lo), "f"(hi)); return r;
}
__device__ __forceinline__ void upk2(u64 v, float& lo, float& hi) {
    asm("mov.b64 {%0, %1}, %2;" : "=f"(lo), "=f"(hi) : "l"(v));
}
__device__ __forceinline__ u64 ffma2(u64 a, u64 b, u64 c) {
    u64 d; asm("fma.rn.f32x2 %0, %1, %2, %3;" : "=l"(d) : "l"(a), "l"(b), "l"(c));
    return d;
}
__device__ __forceinline__ float silu_f(float x) {
    return x / (1.0f + __expf(-x));
}
__device__ __forceinline__ void red_add_v4(float* p, float a, float b, float c, float d) {
    asm volatile("red.global.add.v4.f32 [%0], {%1, %2, %3, %4};"
                 :: "l"(p), "f"(a), "f"(b), "f"(c), "f"(d) : "memory");
}

// ---------------------------------------------------------------------------
// Shared-memory loaders.
//   Ws: weight tile [128][128] row-major (k-major) -> 64 KB
//   As: A tile stored TRANSPOSED As[k][r], k<128, r<64 -> 32 KB
// ---------------------------------------------------------------------------
__device__ __forceinline__ void load_W(float* Ws, const float* __restrict__ W) {
    const float4* src = (const float4*)W;
    float4* dst = (float4*)Ws;
    for (int i = threadIdx.x; i < (DD * DD) / 4; i += 256)
        dst[i] = src[i];
}

__device__ __forceinline__ void load_At(float* As, const float* __restrict__ A, int rowbase) {
    // rows rowbase..rowbase+63, 128 cols, stored As[k*64 + r]
    for (int i = threadIdx.x; i < 64 * 32; i += 256) {
        int r  = i >> 5;       // 0..63
        int kv = i & 31;       // float4 index along k
        float4 v = *(const float4*)(A + (size_t)(rowbase + r) * DD + kv * 4);
        As[(kv * 4 + 0) * 64 + r] = v.x;
        As[(kv * 4 + 1) * 64 + r] = v.y;
        As[(kv * 4 + 2) * 64 + r] = v.z;
        As[(kv * 4 + 3) * 64 + r] = v.w;
    }
}

// ---------------------------------------------------------------------------
// Core 64x128 tile MAC: acc[4][4] (f32x2 pairs = 4 rows x 8 cols per thread)
// Thread map: tc = tid&15 -> c0 = tc*8 ; tr = tid>>4 -> r0 = tr*4
// ---------------------------------------------------------------------------
__device__ __forceinline__ void mm_tile(const float* __restrict__ As,
                                        const float* __restrict__ Ws,
                                        u64 acc[4][4], int r0, int c0) {
#pragma unroll 4
    for (int k = 0; k < DD; k++) {
        const float4 av = *(const float4*)(As + k * 64 + r0);
        const ulonglong2 b01 = *(const ulonglong2*)(Ws + k * DD + c0);
        const ulonglong2 b23 = *(const ulonglong2*)(Ws + k * DD + c0 + 4);
        u64 a0 = pk2(av.x, av.x);
        u64 a1 = pk2(av.y, av.y);
        u64 a2 = pk2(av.z, av.z);
        u64 a3 = pk2(av.w, av.w);
        acc[0][0] = ffma2(a0, b01.x, acc[0][0]); acc[0][1] = ffma2(a0, b01.y, acc[0][1]);
        acc[0][2] = ffma2(a0, b23.x, acc[0][2]); acc[0][3] = ffma2(a0, b23.y, acc[0][3]);
        acc[1][0] = ffma2(a1, b01.x, acc[1][0]); acc[1][1] = ffma2(a1, b01.y, acc[1][1]);
        acc[1][2] = ffma2(a1, b23.x, acc[1][2]); acc[1][3] = ffma2(a1, b23.y, acc[1][3]);
        acc[2][0] = ffma2(a2, b01.x, acc[2][0]); acc[2][1] = ffma2(a2, b01.y, acc[2][1]);
        acc[2][2] = ffma2(a2, b23.x, acc[2][2]); acc[2][3] = ffma2(a2, b23.y, acc[2][3]);
        acc[3][0] = ffma2(a3, b01.x, acc[3][0]); acc[3][1] = ffma2(a3, b01.y, acc[3][1]);
        acc[3][2] = ffma2(a3, b23.x, acc[3][2]); acc[3][3] = ffma2(a3, b23.y, acc[3][3]);
    }
}

// ---------------------------------------------------------------------------
// zero g_agg
// ---------------------------------------------------------------------------
__global__ void zero_kernel(float4* p, int n4) {
    int i = blockIdx.x * blockDim.x + threadIdx.x;
    if (i < n4) p[i] = make_float4(0.f, 0.f, 0.f, 0.f);
}

// ---------------------------------------------------------------------------
// C = [residual +] (A @ W + bias)      (64 rows per block)
// ---------------------------------------------------------------------------
template <bool RES>
__global__ void __launch_bounds__(256)
gemm1_kernel(const float* __restrict__ A, const float* __restrict__ W,
             const float* __restrict__ bias, const float* __restrict__ res,
             float* __restrict__ C) {
    extern __shared__ float sm[];
    float* Ws = sm;               // 128*128
    float* As = sm + DD * DD;     // 128*64
    load_W(Ws, W);
    load_At(As, A, blockIdx.x * 64);
    __syncthreads();

    const int tc = threadIdx.x & 15, tr = threadIdx.x >> 4;
    const int c0 = tc * 8, r0 = tr * 4;

    u64 acc[4][4];
#pragma unroll
    for (int i = 0; i < 4; i++)
#pragma unroll
        for (int j = 0; j < 4; j++)
            acc[i][j] = pk2(bias[c0 + 2 * j], bias[c0 + 2 * j + 1]);

    mm_tile(As, Ws, acc, r0, c0);

#pragma unroll
    for (int i = 0; i < 4; i++) {
        const size_t row = (size_t)blockIdx.x * 64 + r0 + i;
        float v[8];
#pragma unroll
        for (int j = 0; j < 4; j++) upk2(acc[i][j], v[2 * j], v[2 * j + 1]);
        if (RES) {
            float4 ra = *(const float4*)(res + row * DD + c0);
            float4 rb = *(const float4*)(res + row * DD + c0 + 4);
            v[0] += ra.x; v[1] += ra.y; v[2] += ra.z; v[3] += ra.w;
            v[4] += rb.x; v[5] += rb.y; v[6] += rb.z; v[7] += rb.w;
        }
        *(float4*)(C + row * DD + c0)     = make_float4(v[0], v[1], v[2], v[3]);
        *(float4*)(C + row * DD + c0 + 4) = make_float4(v[4], v[5], v[6], v[7]);
    }
}

// ---------------------------------------------------------------------------
// C = silu(A1 @ W1 + A2 @ W2 + bias)   (64 rows per block)
// ---------------------------------------------------------------------------
__global__ void __launch_bounds__(256)
gemm2_silu_kernel(const float* __restrict__ A1, const float* __restrict__ W1,
                  const float* __restrict__ A2, const float* __restrict__ W2,
                  const float* __restrict__ bias, float* __restrict__ C) {
    extern __shared__ float sm[];
    float* W1s = sm;                         // 16384
    float* W2s = sm + 16384;                 // 16384
    float* A1s = sm + 32768;                 // 8192
    float* A2s = sm + 32768 + 8192;          // 8192
    load_W(W1s, W1);
    load_W(W2s, W2);
    load_At(A1s, A1, blockIdx.x * 64);
    load_At(A2s, A2, blockIdx.x * 64);
    __syncthreads();

    const int tc = threadIdx.x & 15, tr = threadIdx.x >> 4;
    const int c0 = tc * 8, r0 = tr * 4;

    u64 acc[4][4];
#pragma unroll
    for (int i = 0; i < 4; i++)
#pragma unroll
        for (int j = 0; j < 4; j++)
            acc[i][j] = pk2(bias[c0 + 2 * j], bias[c0 + 2 * j + 1]);

    mm_tile(A1s, W1s, acc, r0, c0);
    mm_tile(A2s, W2s, acc, r0, c0);

#pragma unroll
    for (int i = 0; i < 4; i++) {
        const size_t row = (size_t)blockIdx.x * 64 + r0 + i;
        float v[8];
#pragma unroll
        for (int j = 0; j < 4; j++) upk2(acc[i][j], v[2 * j], v[2 * j + 1]);
#pragma unroll
        for (int j = 0; j < 8; j++) v[j] = silu_f(v[j]);
        *(float4*)(C + row * DD + c0)     = make_float4(v[0], v[1], v[2], v[3]);
        *(float4*)(C + row * DD + c0 + 4) = make_float4(v[4], v[5], v[6], v[7]);
    }
}

// ---------------------------------------------------------------------------
// Edge stage: msg = silu(EF @ Wb + P[src]) ; red.add to agg[dst]
// ---------------------------------------------------------------------------
__global__ void __launch_bounds__(256)
edge_kernel(const float* __restrict__ EF, const float* __restrict__ Wb,
            const int* __restrict__ src, const int* __restrict__ dst,
            const float* __restrict__ P, float* __restrict__ agg) {
    extern __shared__ float sm[];
    float* Ws = sm;               // 128*128
    float* As = sm + DD * DD;     // 128*64
    __shared__ int s_src[64];
    __shared__ int s_dst[64];

    const int ebase = blockIdx.x * 64;
    load_W(Ws, Wb);
    load_At(As, EF, ebase);
    if (threadIdx.x < 64) {
        s_src[threadIdx.x] = src[ebase + threadIdx.x];
        s_dst[threadIdx.x] = dst[ebase + threadIdx.x];
    }
    __syncthreads();

    const int tc = threadIdx.x & 15, tr = threadIdx.x >> 4;
    const int c0 = tc * 8, r0 = tr * 4;

    u64 acc[4][4];
    const u64 z = pk2(0.f, 0.f);
#pragma unroll
    for (int i = 0; i < 4; i++)
#pragma unroll
        for (int j = 0; j < 4; j++) acc[i][j] = z;

    mm_tile(As, Ws, acc, r0, c0);

#pragma unroll
    for (int i = 0; i < 4; i++) {
        const int e = r0 + i;
        const float* Prow = P + (size_t)s_src[e] * DD + c0;
        float4 pa = *(const float4*)(Prow);
        float4 pb = *(const float4*)(Prow + 4);
        float v[8];
#pragma unroll
        for (int j = 0; j < 4; j++) upk2(acc[i][j], v[2 * j], v[2 * j + 1]);
        v[0] += pa.x; v[1] += pa.y; v[2] += pa.z; v[3] += pa.w;
        v[4] += pb.x; v[5] += pb.y; v[6] += pb.z; v[7] += pb.w;
#pragma unroll
        for (int j = 0; j < 8; j++) v[j] = silu_f(v[j]);
        float* ag = agg + (size_t)s_dst[e] * DD + c0;
        red_add_v4(ag,     v[0], v[1], v[2], v[3]);
        red_add_v4(ag + 4, v[4], v[5], v[6], v[7]);
    }
}

// ---------------------------------------------------------------------------
// launch
// ---------------------------------------------------------------------------
extern "C" void kernel_launch(void* const* d_in, const int* in_sizes, int n_in,
                              void* d_out, int out_size) {
    const float* nodes = (const float*)d_in[0];
    const int*   ei    = (const int*)d_in[1];     // [2, E]: row0=src, row1=dst
    const float* ef    = (const float*)d_in[2];
    const float* mw1   = (const float*)d_in[3];   // [256,128]
    const float* mb1   = (const float*)d_in[4];
    const float* uw1   = (const float*)d_in[5];   // [256,128]
    const float* ub1   = (const float*)d_in[6];
    const float* uw2   = (const float*)d_in[7];   // [128,128]
    const float* ub2   = (const float*)d_in[8];
    float* out = (float*)d_out;

    float *P, *agg, *H;
    cudaGetSymbolAddress((void**)&P,   g_P);
    cudaGetSymbolAddress((void**)&agg, g_agg);
    cudaGetSymbolAddress((void**)&H,   g_H);

    const int SMEM1 = (DD * DD + DD * 64) * (int)sizeof(float);      // 96 KB
    const int SMEM2 = 2 * SMEM1;                                     // 192 KB
    cudaFuncSetAttribute(gemm1_kernel<false>, cudaFuncAttributeMaxDynamicSharedMemorySize, SMEM1);
    cudaFuncSetAttribute(gemm1_kernel<true>,  cudaFuncAttributeMaxDynamicSharedMemorySize, SMEM1);
    cudaFuncSetAttribute(gemm2_silu_kernel,   cudaFuncAttributeMaxDynamicSharedMemorySize, SMEM2);
    cudaFuncSetAttribute(edge_kernel,         cudaFuncAttributeMaxDynamicSharedMemorySize, SMEM1);

    // 0) zero the aggregation buffer
    {
        int n4 = NNODES * DD / 4;
        zero_kernel<<<(n4 + 255) / 256, 256>>>((float4*)agg, n4);
    }
    // 1) P = nodes @ mw1_top + mb1
    gemm1_kernel<false><<<NNODES / 64, 256, SMEM1>>>(nodes, mw1, mb1, nullptr, P);
    // 2) edges: msg = silu(ef @ mw1_bot + P[src]); agg[dst] += msg
    edge_kernel<<<NEDGES / 64, 256, SMEM1>>>(ef, mw1 + DD * DD,
                                             ei, ei + NEDGES, P, agg);
    // 3) H = silu(nodes @ uw1_top + agg @ uw1_bot + ub1)
    gemm2_silu_kernel<<<NNODES / 64, 256, SMEM2>>>(nodes, uw1, agg, uw1 + DD * DD, ub1, H);
    // 4) out = nodes + H @ uw2 + ub2
    gemm1_kernel<true><<<NNODES / 64, 256, SMEM1>>>(H, uw2, ub2, nodes, out);
}

// round 3
// speedup vs baseline: 2.0707x; 2.0707x over previous
#include <cuda_runtime.h>
#include <cuda_bf16.h>
#include <cstdint>

#define DD       128
#define NNODES   40000
#define NEDGES   640000
#define NSM      148
#define NTHREADS 256
#define TILE_M   128

// ---------------- global scratch ----------------
// Weight images: 5 matrices, each a 64KB smem-image: 16 k-chunks x 4KB,
// chunk c<8 = bf16 hi of k[16c..16c+15], c>=8 = bf16 lo. Row-permuted for v4 epilogue.
__device__ __align__(16) char g_Wimg[5][65536];
__device__ float g_P[(size_t)NNODES * DD];
__device__ float g_agg[(size_t)NNODES * DD];
__device__ float g_H[(size_t)NNODES * DD];

// ---------------- layout helpers ----------------
// Within a 4KB chunk: slot for (row r 0..127, k-half h 0..1), 16B each,
// XOR-swizzled so ldmatrix phases are bank-conflict-free.
__host__ __device__ __forceinline__ int img_off(int c, int r, int h) {
    int i = 2 * r + h;
    i ^= (i >> 3) & 1;
    return c * 4096 + (i << 4);
}
// Column permutation: thread's two (nf, nf+1) fragment col-pairs become 4
// physically consecutive columns -> float4/red.v4 epilogue.
__host__ __device__ __forceinline__ int permcol(int n) {
    int nf = (n >> 3) & 3, j = n & 7;
    return (n & ~31) | ((nf >> 1) << 4) | ((j >> 1) << 2) | ((nf & 1) << 1) | (j & 1);
}

__device__ __forceinline__ uint32_t smem_u32(const void* p) {
    uint32_t a;
    asm("{ .reg .u64 t; cvta.to.shared.u64 t, %1; cvt.u32.u64 %0, t; }" : "=r"(a) : "l"(p));
    return a;
}
// ldmatrix x4 address for lane: 16 rows (r16..r16+15) x 16 k of chunk c
__device__ __forceinline__ uint32_t ldm_addr(uint32_t base, int c, int r16, int lane) {
    int r = r16 + ((lane >> 3) & 1) * 8 + (lane & 7);
    int h = lane >> 4;
    int i = 2 * r + h;
    i ^= (i >> 3) & 1;
    return base + c * 4096 + (i << 4);
}

#define LDM4(d, addr) \
    asm volatile("ldmatrix.sync.aligned.m8n8.x4.shared.b16 {%0,%1,%2,%3}, [%4];" \
                 : "=r"((d)[0]), "=r"((d)[1]), "=r"((d)[2]), "=r"((d)[3]) : "r"(addr))

#define MMA(d, a, b0, b1) \
    asm volatile("mma.sync.aligned.m16n8k16.row.col.f32.bf16.bf16.f32 " \
                 "{%0,%1,%2,%3}, {%4,%5,%6,%7}, {%8,%9}, {%0,%1,%2,%3};" \
                 : "+f"((d)[0]), "+f"((d)[1]), "+f"((d)[2]), "+f"((d)[3]) \
                 : "r"((a)[0]), "r"((a)[1]), "r"((a)[2]), "r"((a)[3]), "r"(b0), "r"(b1))

__device__ __forceinline__ float silu_f(float x) { return x / (1.0f + __expf(-x)); }

__device__ __forceinline__ void red_add_v4(float* p, float a, float b, float c, float d) {
    asm volatile("red.global.add.v4.f32 [%0], {%1, %2, %3, %4};"
                 :: "l"(p), "f"(a), "f"(b), "f"(c), "f"(d) : "memory");
}

__device__ __forceinline__ uint32_t pk_bf2(__nv_bfloat16 a, __nv_bfloat16 b) {
    __nv_bfloat162 t = __halves2bfloat162(a, b);
    return *(uint32_t*)&t;
}

// ---------------- prep: split + image-layout weights ----------------
__global__ void prep_kernel(const float* __restrict__ mw1, const float* __restrict__ uw1,
                            const float* __restrict__ uw2) {
    const int which = blockIdx.x;
    const float* W;
    switch (which) {
        case 0: W = mw1; break;
        case 1: W = mw1 + DD * DD; break;
        case 2: W = uw1; break;
        case 3: W = uw1 + DD * DD; break;
        default: W = uw2; break;
    }
    char* img = &g_Wimg[which][0];
    for (int i = threadIdx.x; i < DD * DD; i += blockDim.x) {
        int n = i >> 7, k = i & 127;
        float w = W[k * DD + permcol(n)];
        __nv_bfloat16 hi = __float2bfloat16(w);
        __nv_bfloat16 lo = __float2bfloat16(w - __bfloat162float(hi));
        int c = k >> 4, kk = k & 15, h = kk >> 3, b = kk & 7;
        *(__nv_bfloat16*)(img + img_off(c, n, h) + b * 2)     = hi;
        *(__nv_bfloat16*)(img + img_off(c + 8, n, h) + b * 2) = lo;
    }
}

__global__ void zero_kernel(float4* p, int n4) {
    int i = blockIdx.x * blockDim.x + threadIdx.x;
    if (i < n4) p[i] = make_float4(0.f, 0.f, 0.f, 0.f);
}

// ---------------- main GEMM kernel ----------------
// out[tile 128 x 128] ops: optional BIAS, ADD(addv[row or gathered src]),
// SILU, SCATTER(red.add to dst) else store.
template <bool BIAS, bool ADD, bool GATHER, bool SILU, bool SCATTER>
__global__ void __launch_bounds__(NTHREADS, 1)
tgemm(const float* __restrict__ A, const char* __restrict__ Bimg,
      const float* __restrict__ addv, const float* __restrict__ bias,
      const int* __restrict__ gsrc, const int* __restrict__ gdst,
      float* __restrict__ Out, int nrows) {
    extern __shared__ char sm[];          // [0,64K) B image, [64K,128K) A tile
    __shared__ int s_idx[2 * TILE_M];
    const uint32_t Bs = smem_u32(sm);
    const uint32_t As = Bs + 65536;
    const int tid = threadIdx.x, lane = tid & 31, wid = tid >> 5;
    const int wm = wid & 1, wn = wid >> 1;      // warp tile: rows wm*64+, cols wn*32+

    // load B image once
    for (int i = tid; i < 4096; i += NTHREADS)
        ((uint4*)sm)[i] = __ldg((const uint4*)Bimg + i);
    __syncthreads();

    // cache all Bh fragments in registers for the whole kernel
    uint32_t bh[8][2][4];
#pragma unroll
    for (int c = 0; c < 8; c++)
#pragma unroll
        for (int g = 0; g < 2; g++)
            LDM4(bh[c][g], ldm_addr(Bs, c, wn * 32 + g * 16, lane));

    // bias preload (column-indexed, constant per thread)
    float4 bias0 = make_float4(0, 0, 0, 0), bias1 = bias0;
    if (BIAS) {
        bias0 = __ldg((const float4*)(bias + wn * 32 + (lane & 3) * 4));
        bias1 = __ldg((const float4*)(bias + wn * 32 + 16 + (lane & 3) * 4));
    }

    const int tiles = (nrows + TILE_M - 1) / TILE_M;
    for (int tile = blockIdx.x; tile < tiles; tile += (int)gridDim.x) {
        const long rowbase = (long)tile * TILE_M;

        // ---- convert A tile: fp32 -> [hi|lo] bf16 image in smem ----
        {
            const int r = tid >> 1;
            const int cb = (tid & 1) << 6;
            const long gr = rowbase + r;
            const bool valid = gr < (long)nrows;
            const float4* srcp = (const float4*)(A + gr * DD + cb);
#pragma unroll
            for (int j = 0; j < 8; j++) {
                float x[8];
                if (valid) {
                    float4 u = __ldg(srcp + 2 * j);
                    float4 v = __ldg(srcp + 2 * j + 1);
                    x[0] = u.x; x[1] = u.y; x[2] = u.z; x[3] = u.w;
                    x[4] = v.x; x[5] = v.y; x[6] = v.z; x[7] = v.w;
                } else {
#pragma unroll
                    for (int q = 0; q < 8; q++) x[q] = 0.f;
                }
                __nv_bfloat16 hi[8], lo[8];
#pragma unroll
                for (int q = 0; q < 8; q++) {
                    hi[q] = __float2bfloat16(x[q]);
                    lo[q] = __float2bfloat16(x[q] - __bfloat162float(hi[q]));
                }
                const int col0 = cb + j * 8;
                const int c = col0 >> 4, h = (col0 >> 3) & 1;
                *(uint4*)(sm + 65536 + img_off(c, r, h)) =
                    make_uint4(pk_bf2(hi[0], hi[1]), pk_bf2(hi[2], hi[3]),
                               pk_bf2(hi[4], hi[5]), pk_bf2(hi[6], hi[7]));
                *(uint4*)(sm + 65536 + img_off(c + 8, r, h)) =
                    make_uint4(pk_bf2(lo[0], lo[1]), pk_bf2(lo[2], lo[3]),
                               pk_bf2(lo[4], lo[5]), pk_bf2(lo[6], lo[7]));
            }
        }
        if (GATHER && tid < TILE_M) {
            long gr = rowbase + tid;
            s_idx[tid] = (gr < (long)nrows) ? __ldg(gsrc + gr) : 0;
        }
        if (SCATTER && tid >= TILE_M) {
            int r2 = tid - TILE_M;
            long gr = rowbase + r2;
            s_idx[TILE_M + r2] = (gr < (long)nrows) ? __ldg(gdst + gr) : 0;
        }
        __syncthreads();

        // ---- MMA: acc = Ah*Bh + Ah*Bl + Al*Bh over 8 k16-chunks ----
        float acc[4][4][4];
#pragma unroll
        for (int mf = 0; mf < 4; mf++)
#pragma unroll
            for (int nf = 0; nf < 4; nf++)
#pragma unroll
                for (int q = 0; q < 4; q++) acc[mf][nf][q] = 0.f;

#pragma unroll
        for (int c = 0; c < 8; c++) {
            uint32_t a[4][4];
#pragma unroll
            for (int mf = 0; mf < 4; mf++)
                LDM4(a[mf], ldm_addr(As, c, wm * 64 + mf * 16, lane));
            uint32_t bl[2][4];
#pragma unroll
            for (int g = 0; g < 2; g++)
                LDM4(bl[g], ldm_addr(Bs, 8 + c, wn * 32 + g * 16, lane));
#pragma unroll
            for (int mf = 0; mf < 4; mf++) {
#pragma unroll
                for (int nf = 0; nf < 4; nf++) {
                    MMA(acc[mf][nf], a[mf], bh[c][nf >> 1][nf & 1],
                        bh[c][nf >> 1][(nf & 1) + 2]);
                }
#pragma unroll
                for (int nf = 0; nf < 4; nf++) {
                    MMA(acc[mf][nf], a[mf], bl[nf >> 1][nf & 1],
                        bl[nf >> 1][(nf & 1) + 2]);
                }
            }
            uint32_t a2[4][4];
#pragma unroll
            for (int mf = 0; mf < 4; mf++)
                LDM4(a2[mf], ldm_addr(As, 8 + c, wm * 64 + mf * 16, lane));
#pragma unroll
            for (int mf = 0; mf < 4; mf++)
#pragma unroll
                for (int nf = 0; nf < 4; nf++)
                    MMA(acc[mf][nf], a2[mf], bh[c][nf >> 1][nf & 1],
                        bh[c][nf >> 1][(nf & 1) + 2]);
        }

        // ---- epilogue straight from registers ----
        {
            const int q = lane & 3, ro = lane >> 2;
#pragma unroll
            for (int mf = 0; mf < 4; mf++) {
#pragma unroll
                for (int rh = 0; rh < 2; rh++) {
                    const int r = wm * 64 + mf * 16 + rh * 8 + ro;
                    const long gr = rowbase + r;
                    if (gr >= (long)nrows) continue;
                    const long arow = GATHER ? (long)s_idx[r] : gr;
                    const long orow = SCATTER ? (long)s_idx[TILE_M + r] : gr;
#pragma unroll
                    for (int p = 0; p < 2; p++) {
                        const int cc = wn * 32 + p * 16 + q * 4;
                        float v0 = acc[mf][2 * p][2 * rh];
                        float v1 = acc[mf][2 * p][2 * rh + 1];
                        float v2 = acc[mf][2 * p + 1][2 * rh];
                        float v3 = acc[mf][2 * p + 1][2 * rh + 1];
                        if (ADD) {
                            float4 t = __ldg((const float4*)(addv + arow * DD + cc));
                            v0 += t.x; v1 += t.y; v2 += t.z; v3 += t.w;
                        }
                        if (BIAS) {
                            float4 b = p ? bias1 : bias0;
                            v0 += b.x; v1 += b.y; v2 += b.z; v3 += b.w;
                        }
                        if (SILU) {
                            v0 = silu_f(v0); v1 = silu_f(v1);
                            v2 = silu_f(v2); v3 = silu_f(v3);
                        }
                        float* op = Out + orow * DD + cc;
                        if (SCATTER) red_add_v4(op, v0, v1, v2, v3);
                        else *(float4*)op = make_float4(v0, v1, v2, v3);
                    }
                }
            }
        }
        __syncthreads();
    }
}

// ---------------- launch ----------------
extern "C" void kernel_launch(void* const* d_in, const int* in_sizes, int n_in,
                              void* d_out, int out_size) {
    const float* nodes = (const float*)d_in[0];
    const int*   ei    = (const int*)d_in[1];   // [2,E]: row0=src, row1=dst
    const float* ef    = (const float*)d_in[2];
    const float* mw1   = (const float*)d_in[3];
    const float* mb1   = (const float*)d_in[4];
    const float* uw1   = (const float*)d_in[5];
    const float* ub1   = (const float*)d_in[6];
    const float* uw2   = (const float*)d_in[7];
    const float* ub2   = (const float*)d_in[8];
    float* out = (float*)d_out;

    char* Wimg;
    float *P, *agg, *H;
    cudaGetSymbolAddress((void**)&Wimg, g_Wimg);
    cudaGetSymbolAddress((void**)&P,    g_P);
    cudaGetSymbolAddress((void**)&agg,  g_agg);
    cudaGetSymbolAddress((void**)&H,    g_H);

    const int SMEM = 131072;
    cudaFuncSetAttribute(tgemm<true,  false, false, false, false>,
                         cudaFuncAttributeMaxDynamicSharedMemorySize, SMEM);
    cudaFuncSetAttribute(tgemm<false, true,  true,  true,  true>,
                         cudaFuncAttributeMaxDynamicSharedMemorySize, SMEM);
    cudaFuncSetAttribute(tgemm<false, false, false, false, false>,
                         cudaFuncAttributeMaxDynamicSharedMemorySize, SMEM);
    cudaFuncSetAttribute(tgemm<true,  true,  false, true,  false>,
                         cudaFuncAttributeMaxDynamicSharedMemorySize, SMEM);
    cudaFuncSetAttribute(tgemm<true,  true,  false, false, false>,
                         cudaFuncAttributeMaxDynamicSharedMemorySize, SMEM);

    // 0) weight images + zero agg
    prep_kernel<<<5, 256>>>(mw1, uw1, uw2);
    {
        int n4 = NNODES * DD / 4;
        zero_kernel<<<(n4 + 255) / 256, 256>>>((float4*)agg, n4);
    }
    // 1) P = nodes @ mw1_top + mb1
    tgemm<true, false, false, false, false><<<NSM, NTHREADS, SMEM>>>(
        nodes, Wimg + 0 * 65536, nullptr, mb1, nullptr, nullptr, P, NNODES);
    // 2) agg[dst] += silu(ef @ mw1_bot + P[src])
    tgemm<false, true, true, true, true><<<NSM, NTHREADS, SMEM>>>(
        ef, Wimg + 1 * 65536, P, nullptr, ei, ei + NEDGES, agg, NEDGES);
    // 3) T = nodes @ uw1_top      (reuse g_P as T)
    tgemm<false, false, false, false, false><<<NSM, NTHREADS, SMEM>>>(
        nodes, Wimg + 2 * 65536, nullptr, nullptr, nullptr, nullptr, P, NNODES);
    // 4) H = silu(agg @ uw1_bot + T + ub1)
    tgemm<true, true, false, true, false><<<NSM, NTHREADS, SMEM>>>(
        agg, Wimg + 3 * 65536, P, ub1, nullptr, nullptr, H, NNODES);
    // 5) out = H @ uw2 + nodes + ub2
    tgemm<true, true, false, false, false><<<NSM, NTHREADS, SMEM>>>(
        H, Wimg + 4 * 65536, nodes, ub2, nullptr, nullptr, out, NNODES);
}

// round 4
// speedup vs baseline: 2.8753x; 1.3886x over previous
#include <cuda_runtime.h>
#include <cuda_bf16.h>
#include <cstdint>

#define DD       128
#define NNODES   40000
#define NEDGES   640000
#define NSM      148
#define NTHREADS 256
#define TILE_M   64
#define NGRID    (2 * NSM)

// ---------------- global scratch ----------------
// Weight images: 5 matrices, each 64KB: 16 k-chunks x 4KB (128 rows),
// chunk c<8 = bf16 hi of k[16c..16c+15], c>=8 = bf16 lo. Row-permuted.
__device__ __align__(16) char g_Wimg[5][65536];
__device__ float g_P[(size_t)NNODES * DD];
__device__ float g_agg[(size_t)NNODES * DD];
__device__ float g_H[(size_t)NNODES * DD];

// ---------------- layout helpers ----------------
// B image (128 rows/chunk, 4KB/chunk), XOR-swizzled 16B slots
__host__ __device__ __forceinline__ int img_offB(int c, int r, int h) {
    int i = 2 * r + h;
    i ^= (i >> 3) & 1;
    return c * 4096 + (i << 4);
}
// A image (64 rows/chunk, 2KB/chunk)
__device__ __forceinline__ int img_offA(int c, int r, int h) {
    int i = 2 * r + h;
    i ^= (i >> 3) & 1;
    return c * 2048 + (i << 4);
}
// Column permutation: maps warp fragment col-pairs to 4 consecutive columns.
__host__ __device__ __forceinline__ int permcol(int n) {
    int nf = (n >> 3) & 3, j = n & 7;
    return (n & ~31) | ((nf >> 1) << 4) | ((j >> 1) << 2) | ((nf & 1) << 1) | (j & 1);
}

__device__ __forceinline__ uint32_t smem_u32(const void* p) {
    uint32_t a;
    asm("{ .reg .u64 t; cvta.to.shared.u64 t, %1; cvt.u32.u64 %0, t; }" : "=r"(a) : "l"(p));
    return a;
}
__device__ __forceinline__ uint32_t ldm_addrB(uint32_t base, int c, int r16, int lane) {
    int r = r16 + ((lane >> 3) & 1) * 8 + (lane & 7);
    int h = lane >> 4;
    int i = 2 * r + h;
    i ^= (i >> 3) & 1;
    return base + c * 4096 + (i << 4);
}
__device__ __forceinline__ uint32_t ldm_addrA(uint32_t base, int c, int r16, int lane) {
    int r = r16 + ((lane >> 3) & 1) * 8 + (lane & 7);
    int h = lane >> 4;
    int i = 2 * r + h;
    i ^= (i >> 3) & 1;
    return base + c * 2048 + (i << 4);
}

#define LDM4(d, addr) \
    asm volatile("ldmatrix.sync.aligned.m8n8.x4.shared.b16 {%0,%1,%2,%3}, [%4];" \
                 : "=r"((d)[0]), "=r"((d)[1]), "=r"((d)[2]), "=r"((d)[3]) : "r"(addr))

#define MMA(d, a, b0, b1) \
    asm volatile("mma.sync.aligned.m16n8k16.row.col.f32.bf16.bf16.f32 " \
                 "{%0,%1,%2,%3}, {%4,%5,%6,%7}, {%8,%9}, {%0,%1,%2,%3};" \
                 : "+f"((d)[0]), "+f"((d)[1]), "+f"((d)[2]), "+f"((d)[3]) \
                 : "r"((a)[0]), "r"((a)[1]), "r"((a)[2]), "r"((a)[3]), "r"(b0), "r"(b1))

__device__ __forceinline__ float silu_f(float x) { return x / (1.0f + __expf(-x)); }

__device__ __forceinline__ void red_add_v4(float* p, float a, float b, float c, float d) {
    asm volatile("red.global.add.v4.f32 [%0], {%1, %2, %3, %4};"
                 :: "l"(p), "f"(a), "f"(b), "f"(c), "f"(d) : "memory");
}

__device__ __forceinline__ uint32_t pk_bf2(__nv_bfloat16 a, __nv_bfloat16 b) {
    __nv_bfloat162 t = __halves2bfloat162(a, b);
    return *(uint32_t*)&t;
}

// ---------------- prep: split + image-layout weights ----------------
__global__ void prep_kernel(const float* __restrict__ mw1, const float* __restrict__ uw1,
                            const float* __restrict__ uw2) {
    const int which = blockIdx.x;
    const float* W;
    switch (which) {
        case 0: W = mw1; break;
        case 1: W = mw1 + DD * DD; break;
        case 2: W = uw1; break;
        case 3: W = uw1 + DD * DD; break;
        default: W = uw2; break;
    }
    char* img = &g_Wimg[which][0];
    for (int i = threadIdx.x; i < DD * DD; i += blockDim.x) {
        int n = i >> 7, k = i & 127;
        float w = W[k * DD + permcol(n)];
        __nv_bfloat16 hi = __float2bfloat16(w);
        __nv_bfloat16 lo = __float2bfloat16(w - __bfloat162float(hi));
        int c = k >> 4, kk = k & 15, h = kk >> 3, b = kk & 7;
        *(__nv_bfloat16*)(img + img_offB(c, n, h) + b * 2)     = hi;
        *(__nv_bfloat16*)(img + img_offB(c + 8, n, h) + b * 2) = lo;
    }
}

__global__ void zero_kernel(float4* p, int n4) {
    int i = blockIdx.x * blockDim.x + threadIdx.x;
    if (i < n4) p[i] = make_float4(0.f, 0.f, 0.f, 0.f);
}

// ---------------- main GEMM kernel ----------------
// 64-row tiles; smem/CTA = 64KB B + 32KB A -> 2 CTAs/SM.
template <bool BIAS, bool ADD, bool GATHER, bool SILU, bool SCATTER>
__global__ void __launch_bounds__(NTHREADS, 2)
tgemm(const float* __restrict__ A, const char* __restrict__ Bimg,
      const float* __restrict__ addv, const float* __restrict__ bias,
      const int* __restrict__ gsrc, const int* __restrict__ gdst,
      float* __restrict__ Out, int nrows) {
    extern __shared__ char sm[];          // [0,64K) B image, [64K,96K) A tile
    __shared__ int s_idx[2 * TILE_M];
    const uint32_t Bs = smem_u32(sm);
    const uint32_t As = Bs + 65536;
    const int tid = threadIdx.x, lane = tid & 31, wid = tid >> 5;
    const int wm = wid & 1, wn = wid >> 1;      // warp tile: rows wm*32+, cols wn*32+

    // load B image once
    for (int i = tid; i < 4096; i += NTHREADS)
        ((uint4*)sm)[i] = __ldg((const uint4*)Bimg + i);

    // bias preload (column-indexed, constant per thread)
    float4 bias0 = make_float4(0, 0, 0, 0), bias1 = bias0;
    if (BIAS) {
        bias0 = __ldg((const float4*)(bias + wn * 32 + (lane & 3) * 4));
        bias1 = __ldg((const float4*)(bias + wn * 32 + 16 + (lane & 3) * 4));
    }
    __syncthreads();

    const int tiles = (nrows + TILE_M - 1) / TILE_M;
    for (int tile = blockIdx.x; tile < tiles; tile += (int)gridDim.x) {
        const long rowbase = (long)tile * TILE_M;

        // ---- convert A tile: fp32 -> [hi|lo] bf16 image in smem ----
        {
            const int r = tid >> 2;                 // 0..63
            const int cseg = (tid & 3) << 5;        // 0,32,64,96
            const long gr = rowbase + r;
            const bool valid = gr < (long)nrows;
            const float4* srcp = (const float4*)(A + gr * DD + cseg);
#pragma unroll
            for (int j = 0; j < 4; j++) {
                float x[8];
                if (valid) {
                    float4 u = __ldg(srcp + 2 * j);
                    float4 v = __ldg(srcp + 2 * j + 1);
                    x[0] = u.x; x[1] = u.y; x[2] = u.z; x[3] = u.w;
                    x[4] = v.x; x[5] = v.y; x[6] = v.z; x[7] = v.w;
                } else {
#pragma unroll
                    for (int q = 0; q < 8; q++) x[q] = 0.f;
                }
                __nv_bfloat16 hi[8], lo[8];
#pragma unroll
                for (int q = 0; q < 8; q++) {
                    hi[q] = __float2bfloat16(x[q]);
                    lo[q] = __float2bfloat16(x[q] - __bfloat162float(hi[q]));
                }
                const int col0 = cseg + j * 8;
                const int c = col0 >> 4, h = (col0 >> 3) & 1;
                *(uint4*)(sm + 65536 + img_offA(c, r, h)) =
                    make_uint4(pk_bf2(hi[0], hi[1]), pk_bf2(hi[2], hi[3]),
                               pk_bf2(hi[4], hi[5]), pk_bf2(hi[6], hi[7]));
                *(uint4*)(sm + 65536 + img_offA(c + 8, r, h)) =
                    make_uint4(pk_bf2(lo[0], lo[1]), pk_bf2(lo[2], lo[3]),
                               pk_bf2(lo[4], lo[5]), pk_bf2(lo[6], lo[7]));
            }
        }
        if (GATHER && tid < TILE_M) {
            long gr = rowbase + tid;
            s_idx[tid] = (gr < (long)nrows) ? __ldg(gsrc + gr) : 0;
        }
        if (SCATTER && tid >= TILE_M && tid < 2 * TILE_M) {
            int r2 = tid - TILE_M;
            long gr = rowbase + r2;
            s_idx[TILE_M + r2] = (gr < (long)nrows) ? __ldg(gdst + gr) : 0;
        }
        __syncthreads();

        // ---- MMA: acc = Ah*Bh + Ah*Bl + Al*Bh over 8 k16-chunks ----
        float acc[2][4][4];
#pragma unroll
        for (int mf = 0; mf < 2; mf++)
#pragma unroll
            for (int nf = 0; nf < 4; nf++)
#pragma unroll
                for (int q = 0; q < 4; q++) acc[mf][nf][q] = 0.f;

#pragma unroll
        for (int c = 0; c < 8; c++) {
            uint32_t bh[2][4], bl[2][4], a[2][4], a2[2][4];
#pragma unroll
            for (int g = 0; g < 2; g++)
                LDM4(bh[g], ldm_addrB(Bs, c, wn * 32 + g * 16, lane));
#pragma unroll
            for (int mf = 0; mf < 2; mf++)
                LDM4(a[mf], ldm_addrA(As, c, wm * 32 + mf * 16, lane));
#pragma unroll
            for (int g = 0; g < 2; g++)
                LDM4(bl[g], ldm_addrB(Bs, 8 + c, wn * 32 + g * 16, lane));
#pragma unroll
            for (int mf = 0; mf < 2; mf++)
                LDM4(a2[mf], ldm_addrA(As, 8 + c, wm * 32 + mf * 16, lane));

#pragma unroll
            for (int mf = 0; mf < 2; mf++)
#pragma unroll
                for (int nf = 0; nf < 4; nf++)
                    MMA(acc[mf][nf], a[mf], bh[nf >> 1][nf & 1],
                        bh[nf >> 1][(nf & 1) + 2]);
#pragma unroll
            for (int mf = 0; mf < 2; mf++)
#pragma unroll
                for (int nf = 0; nf < 4; nf++)
                    MMA(acc[mf][nf], a[mf], bl[nf >> 1][nf & 1],
                        bl[nf >> 1][(nf & 1) + 2]);
#pragma unroll
            for (int mf = 0; mf < 2; mf++)
#pragma unroll
                for (int nf = 0; nf < 4; nf++)
                    MMA(acc[mf][nf], a2[mf], bh[nf >> 1][nf & 1],
                        bh[nf >> 1][(nf & 1) + 2]);
        }

        // ---- epilogue straight from registers ----
        {
            const int q = lane & 3, ro = lane >> 2;
#pragma unroll
            for (int mf = 0; mf < 2; mf++) {
#pragma unroll
                for (int rh = 0; rh < 2; rh++) {
                    const int r = wm * 32 + mf * 16 + rh * 8 + ro;
                    const long gr = rowbase + r;
                    if (gr >= (long)nrows) continue;
                    const long arow = GATHER ? (long)s_idx[r] : gr;
                    const long orow = SCATTER ? (long)s_idx[TILE_M + r] : gr;
#pragma unroll
                    for (int p = 0; p < 2; p++) {
                        const int cc = wn * 32 + p * 16 + q * 4;
                        float v0 = acc[mf][2 * p][2 * rh];
                        float v1 = acc[mf][2 * p][2 * rh + 1];
                        float v2 = acc[mf][2 * p + 1][2 * rh];
                        float v3 = acc[mf][2 * p + 1][2 * rh + 1];
                        if (ADD) {
                            float4 t = __ldg((const float4*)(addv + arow * DD + cc));
                            v0 += t.x; v1 += t.y; v2 += t.z; v3 += t.w;
                        }
                        if (BIAS) {
                            float4 b = p ? bias1 : bias0;
                            v0 += b.x; v1 += b.y; v2 += b.z; v3 += b.w;
                        }
                        if (SILU) {
                            v0 = silu_f(v0); v1 = silu_f(v1);
                            v2 = silu_f(v2); v3 = silu_f(v3);
                        }
                        float* op = Out + orow * DD + cc;
                        if (SCATTER) red_add_v4(op, v0, v1, v2, v3);
                        else *(float4*)op = make_float4(v0, v1, v2, v3);
                    }
                }
            }
        }
        __syncthreads();
    }
}

// ---------------- launch ----------------
extern "C" void kernel_launch(void* const* d_in, const int* in_sizes, int n_in,
                              void* d_out, int out_size) {
    const float* nodes = (const float*)d_in[0];
    const int*   ei    = (const int*)d_in[1];   // [2,E]: row0=src, row1=dst
    const float* ef    = (const float*)d_in[2];
    const float* mw1   = (const float*)d_in[3];
    const float* mb1   = (const float*)d_in[4];
    const float* uw1   = (const float*)d_in[5];
    const float* ub1   = (const float*)d_in[6];
    const float* uw2   = (const float*)d_in[7];
    const float* ub2   = (const float*)d_in[8];
    float* out = (float*)d_out;

    char* Wimg;
    float *P, *agg, *H;
    cudaGetSymbolAddress((void**)&Wimg, g_Wimg);
    cudaGetSymbolAddress((void**)&P,    g_P);
    cudaGetSymbolAddress((void**)&agg,  g_agg);
    cudaGetSymbolAddress((void**)&H,    g_H);

    const int SMEM = 98304;   // 64KB B + 32KB A
    cudaFuncSetAttribute(tgemm<true,  false, false, false, false>,
                         cudaFuncAttributeMaxDynamicSharedMemorySize, SMEM);
    cudaFuncSetAttribute(tgemm<false, true,  true,  true,  true>,
                         cudaFuncAttributeMaxDynamicSharedMemorySize, SMEM);
    cudaFuncSetAttribute(tgemm<false, false, false, false, false>,
                         cudaFuncAttributeMaxDynamicSharedMemorySize, SMEM);
    cudaFuncSetAttribute(tgemm<true,  true,  false, true,  false>,
                         cudaFuncAttributeMaxDynamicSharedMemorySize, SMEM);
    cudaFuncSetAttribute(tgemm<true,  true,  false, false, false>,
                         cudaFuncAttributeMaxDynamicSharedMemorySize, SMEM);

    // 0) weight images + zero agg
    prep_kernel<<<5, 256>>>(mw1, uw1, uw2);
    {
        int n4 = NNODES * DD / 4;
        zero_kernel<<<(n4 + 255) / 256, 256>>>((float4*)agg, n4);
    }
    // 1) P = nodes @ mw1_top + mb1
    tgemm<true, false, false, false, false><<<NGRID, NTHREADS, SMEM>>>(
        nodes, Wimg + 0 * 65536, nullptr, mb1, nullptr, nullptr, P, NNODES);
    // 2) agg[dst] += silu(ef @ mw1_bot + P[src])
    tgemm<false, true, true, true, true><<<NGRID, NTHREADS, SMEM>>>(
        ef, Wimg + 1 * 65536, P, nullptr, ei, ei + NEDGES, agg, NEDGES);
    // 3) T = nodes @ uw1_top      (reuse g_P as T)
    tgemm<false, false, false, false, false><<<NGRID, NTHREADS, SMEM>>>(
        nodes, Wimg + 2 * 65536, nullptr, nullptr, nullptr, nullptr, P, NNODES);
    // 4) H = silu(agg @ uw1_bot + T + ub1)
    tgemm<true, true, false, true, false><<<NGRID, NTHREADS, SMEM>>>(
        agg, Wimg + 3 * 65536, P, ub1, nullptr, nullptr, H, NNODES);
    // 5) out = H @ uw2 + nodes + ub2
    tgemm<true, true, false, false, false><<<NGRID, NTHREADS, SMEM>>>(
        H, Wimg + 4 * 65536, nodes, ub2, nullptr, nullptr, out, NNODES);
}

// round 5
// speedup vs baseline: 3.3155x; 1.1531x over previous
#include <cuda_runtime.h>
#include <cuda_fp16.h>
#include <cstdint>

#define DD       128
#define NNODES   40000
#define NEDGES   640000
#define NSM      148
#define NTHREADS 256
#define TILE_M   128
#define NGRID    (2 * NSM)

// ---------------- global scratch ----------------
// Weight images: 5 matrices, each 64KB: 16 k-chunks x 4KB (128 rows),
// chunk c<8 = fp16 hi of k[16c..16c+15], c>=8 = fp16 lo (residual). Row-permuted.
__device__ __align__(16) char g_Wimg[5][65536];
__device__ float g_P[(size_t)NNODES * DD];
__device__ float g_agg[(size_t)NNODES * DD];
__device__ float g_H[(size_t)NNODES * DD];

// ---------------- layout helpers ----------------
// image chunk: 128 rows x 16 k fp16 = 4KB; 16B slot per (row, k-half),
// XOR-swizzled for conflict-free ldmatrix.
__host__ __device__ __forceinline__ int img_off(int c, int r, int h) {
    int i = 2 * r + h;
    i ^= (i >> 3) & 1;
    return c * 4096 + (i << 4);
}
// Column permutation: warp fragment col-pairs -> 4 consecutive physical columns.
__host__ __device__ __forceinline__ int permcol(int n) {
    int nf = (n >> 3) & 3, j = n & 7;
    return (n & ~31) | ((nf >> 1) << 4) | ((j >> 1) << 2) | ((nf & 1) << 1) | (j & 1);
}

__device__ __forceinline__ uint32_t smem_u32(const void* p) {
    uint32_t a;
    asm("{ .reg .u64 t; cvta.to.shared.u64 t, %1; cvt.u32.u64 %0, t; }" : "=r"(a) : "l"(p));
    return a;
}
__device__ __forceinline__ uint32_t ldm_addr(uint32_t base, int c, int r16, int lane) {
    int r = r16 + ((lane >> 3) & 1) * 8 + (lane & 7);
    int h = lane >> 4;
    int i = 2 * r + h;
    i ^= (i >> 3) & 1;
    return base + c * 4096 + (i << 4);
}

#define LDM4(d, addr) \
    asm volatile("ldmatrix.sync.aligned.m8n8.x4.shared.b16 {%0,%1,%2,%3}, [%4];" \
                 : "=r"((d)[0]), "=r"((d)[1]), "=r"((d)[2]), "=r"((d)[3]) : "r"(addr))

#define MMA(d, a, b0, b1) \
    asm volatile("mma.sync.aligned.m16n8k16.row.col.f32.f16.f16.f32 " \
                 "{%0,%1,%2,%3}, {%4,%5,%6,%7}, {%8,%9}, {%0,%1,%2,%3};" \
                 : "+f"((d)[0]), "+f"((d)[1]), "+f"((d)[2]), "+f"((d)[3]) \
                 : "r"((a)[0]), "r"((a)[1]), "r"((a)[2]), "r"((a)[3]), "r"(b0), "r"(b1))

__device__ __forceinline__ float silu_f(float x) { return x / (1.0f + __expf(-x)); }

__device__ __forceinline__ void red_add_v4(float* p, float a, float b, float c, float d) {
    asm volatile("red.global.add.v4.f32 [%0], {%1, %2, %3, %4};"
                 :: "l"(p), "f"(a), "f"(b), "f"(c), "f"(d) : "memory");
}

__device__ __forceinline__ uint32_t pk_h2(__half a, __half b) {
    __half2 t = __halves2half2(a, b);
    return *(uint32_t*)&t;
}

// ---------------- prep: split + image-layout weights (fp16 hi/lo) ----------------
__global__ void prep_kernel(const float* __restrict__ mw1, const float* __restrict__ uw1,
                            const float* __restrict__ uw2) {
    const int which = blockIdx.x;
    const float* W;
    switch (which) {
        case 0: W = mw1; break;
        case 1: W = mw1 + DD * DD; break;
        case 2: W = uw1; break;
        case 3: W = uw1 + DD * DD; break;
        default: W = uw2; break;
    }
    char* img = &g_Wimg[which][0];
    for (int i = threadIdx.x; i < DD * DD; i += blockDim.x) {
        int n = i >> 7, k = i & 127;
        float w = W[k * DD + permcol(n)];
        __half hi = __float2half_rn(w);
        __half lo = __float2half_rn(w - __half2float(hi));
        int c = k >> 4, kk = k & 15, h = kk >> 3, b = kk & 7;
        *(__half*)(img + img_off(c, n, h) + b * 2)     = hi;
        *(__half*)(img + img_off(c + 8, n, h) + b * 2) = lo;
    }
}

__global__ void zero_kernel(float4* p, int n4) {
    int i = blockIdx.x * blockDim.x + threadIdx.x;
    if (i < n4) p[i] = make_float4(0.f, 0.f, 0.f, 0.f);
}

// ---------------- main GEMM kernel ----------------
// 128-row tiles; smem/CTA = 64KB B(hi+lo) + 32KB A(single fp16) -> 2 CTAs/SM.
// Warp tile 64x32 (wm = wid&1 rows, wn = wid>>1 cols). 2-pass: acc = A*Bh + A*Bl.
template <bool BIAS, bool ADD, bool GATHER, bool SILU, bool SCATTER>
__global__ void __launch_bounds__(NTHREADS, 2)
tgemm(const float* __restrict__ A, const char* __restrict__ Bimg,
      const float* __restrict__ addv, const float* __restrict__ bias,
      const int* __restrict__ gsrc, const int* __restrict__ gdst,
      float* __restrict__ Out, int nrows) {
    extern __shared__ char sm[];          // [0,64K) B image, [64K,96K) A image
    __shared__ int s_idx[2 * TILE_M];
    const uint32_t Bs = smem_u32(sm);
    const uint32_t As = Bs + 65536;
    const int tid = threadIdx.x, lane = tid & 31, wid = tid >> 5;
    const int wm = wid & 1, wn = wid >> 1;   // rows wm*64+, cols wn*32+

    // load B image once
    for (int i = tid; i < 4096; i += NTHREADS)
        ((uint4*)sm)[i] = __ldg((const uint4*)Bimg + i);

    // bias preload (column-indexed, constant per thread)
    float4 bias0 = make_float4(0, 0, 0, 0), bias1 = bias0;
    if (BIAS) {
        bias0 = __ldg((const float4*)(bias + wn * 32 + (lane & 3) * 4));
        bias1 = __ldg((const float4*)(bias + wn * 32 + 16 + (lane & 3) * 4));
    }
    __syncthreads();

    const int tiles = (nrows + TILE_M - 1) / TILE_M;
    for (int tile = blockIdx.x; tile < tiles; tile += (int)gridDim.x) {
        const long rowbase = (long)tile * TILE_M;

        // ---- convert A tile: fp32 -> fp16 image in smem ----
        {
            const int r = tid >> 1;                // 0..127
            const int cseg = (tid & 1) << 6;       // 0 or 64
            const long gr = rowbase + r;
            const bool valid = gr < (long)nrows;
            const float4* srcp = (const float4*)(A + gr * DD + cseg);
#pragma unroll
            for (int j = 0; j < 8; j++) {
                float x[8];
                if (valid) {
                    float4 u = __ldg(srcp + 2 * j);
                    float4 v = __ldg(srcp + 2 * j + 1);
                    x[0] = u.x; x[1] = u.y; x[2] = u.z; x[3] = u.w;
                    x[4] = v.x; x[5] = v.y; x[6] = v.z; x[7] = v.w;
                } else {
#pragma unroll
                    for (int q = 0; q < 8; q++) x[q] = 0.f;
                }
                const int col0 = cseg + j * 8;
                const int c = col0 >> 4, h = (col0 >> 3) & 1;
                *(uint4*)(sm + 65536 + img_off(c, r, h)) = make_uint4(
                    pk_h2(__float2half_rn(x[0]), __float2half_rn(x[1])),
                    pk_h2(__float2half_rn(x[2]), __float2half_rn(x[3])),
                    pk_h2(__float2half_rn(x[4]), __float2half_rn(x[5])),
                    pk_h2(__float2half_rn(x[6]), __float2half_rn(x[7])));
            }
        }
        if (GATHER && tid < TILE_M) {
            long gr = rowbase + tid;
            s_idx[tid] = (gr < (long)nrows) ? __ldg(gsrc + gr) : 0;
        }
        if (SCATTER && tid >= TILE_M && tid < 2 * TILE_M) {
            int r2 = tid - TILE_M;
            long gr = rowbase + r2;
            s_idx[TILE_M + r2] = (gr < (long)nrows) ? __ldg(gdst + gr) : 0;
        }
        __syncthreads();

        // ---- MMA: acc = A*Bh + A*Bl over 8 k16-chunks ----
        float acc[4][4][4];
#pragma unroll
        for (int mf = 0; mf < 4; mf++)
#pragma unroll
            for (int nf = 0; nf < 4; nf++)
#pragma unroll
                for (int q = 0; q < 4; q++) acc[mf][nf][q] = 0.f;

#pragma unroll
        for (int c = 0; c < 8; c++) {
            uint32_t a[4][4], bh[2][4], bl[2][4];
#pragma unroll
            for (int mf = 0; mf < 4; mf++)
                LDM4(a[mf], ldm_addr(As, c, wm * 64 + mf * 16, lane));
#pragma unroll
            for (int g = 0; g < 2; g++)
                LDM4(bh[g], ldm_addr(Bs, c, wn * 32 + g * 16, lane));
#pragma unroll
            for (int g = 0; g < 2; g++)
                LDM4(bl[g], ldm_addr(Bs, 8 + c, wn * 32 + g * 16, lane));

#pragma unroll
            for (int mf = 0; mf < 4; mf++)
#pragma unroll
                for (int nf = 0; nf < 4; nf++)
                    MMA(acc[mf][nf], a[mf], bh[nf >> 1][nf & 1],
                        bh[nf >> 1][(nf & 1) + 2]);
#pragma unroll
            for (int mf = 0; mf < 4; mf++)
#pragma unroll
                for (int nf = 0; nf < 4; nf++)
                    MMA(acc[mf][nf], a[mf], bl[nf >> 1][nf & 1],
                        bl[nf >> 1][(nf & 1) + 2]);
        }

        // ---- epilogue straight from registers ----
        {
            const int q = lane & 3, ro = lane >> 2;
#pragma unroll
            for (int mf = 0; mf < 4; mf++) {
#pragma unroll
                for (int rh = 0; rh < 2; rh++) {
                    const int r = wm * 64 + mf * 16 + rh * 8 + ro;
                    const long gr = rowbase + r;
                    if (gr >= (long)nrows) continue;
                    const long arow = GATHER ? (long)s_idx[r] : gr;
                    const long orow = SCATTER ? (long)s_idx[TILE_M + r] : gr;
#pragma unroll
                    for (int p = 0; p < 2; p++) {
                        const int cc = wn * 32 + p * 16 + q * 4;
                        float v0 = acc[mf][2 * p][2 * rh];
                        float v1 = acc[mf][2 * p][2 * rh + 1];
                        float v2 = acc[mf][2 * p + 1][2 * rh];
                        float v3 = acc[mf][2 * p + 1][2 * rh + 1];
                        if (ADD) {
                            float4 t = __ldg((const float4*)(addv + arow * DD + cc));
                            v0 += t.x; v1 += t.y; v2 += t.z; v3 += t.w;
                        }
                        if (BIAS) {
                            float4 b = p ? bias1 : bias0;
                            v0 += b.x; v1 += b.y; v2 += b.z; v3 += b.w;
                        }
                        if (SILU) {
                            v0 = silu_f(v0); v1 = silu_f(v1);
                            v2 = silu_f(v2); v3 = silu_f(v3);
                        }
                        float* op = Out + orow * DD + cc;
                        if (SCATTER) red_add_v4(op, v0, v1, v2, v3);
                        else *(float4*)op = make_float4(v0, v1, v2, v3);
                    }
                }
            }
        }
        __syncthreads();
    }
}

// ---------------- launch ----------------
extern "C" void kernel_launch(void* const* d_in, const int* in_sizes, int n_in,
                              void* d_out, int out_size) {
    const float* nodes = (const float*)d_in[0];
    const int*   ei    = (const int*)d_in[1];   // [2,E]: row0=src, row1=dst
    const float* ef    = (const float*)d_in[2];
    const float* mw1   = (const float*)d_in[3];
    const float* mb1   = (const float*)d_in[4];
    const float* uw1   = (const float*)d_in[5];
    const float* ub1   = (const float*)d_in[6];
    const float* uw2   = (const float*)d_in[7];
    const float* ub2   = (const float*)d_in[8];
    float* out = (float*)d_out;

    char* Wimg;
    float *P, *agg, *H;
    cudaGetSymbolAddress((void**)&Wimg, g_Wimg);
    cudaGetSymbolAddress((void**)&P,    g_P);
    cudaGetSymbolAddress((void**)&agg,  g_agg);
    cudaGetSymbolAddress((void**)&H,    g_H);

    const int SMEM = 98304;   // 64KB B + 32KB A
    cudaFuncSetAttribute(tgemm<true,  false, false, false, false>,
                         cudaFuncAttributeMaxDynamicSharedMemorySize, SMEM);
    cudaFuncSetAttribute(tgemm<false, true,  true,  true,  true>,
                         cudaFuncAttributeMaxDynamicSharedMemorySize, SMEM);
    cudaFuncSetAttribute(tgemm<false, false, false, false, false>,
                         cudaFuncAttributeMaxDynamicSharedMemorySize, SMEM);
    cudaFuncSetAttribute(tgemm<true,  true,  false, true,  false>,
                         cudaFuncAttributeMaxDynamicSharedMemorySize, SMEM);
    cudaFuncSetAttribute(tgemm<true,  true,  false, false, false>,
                         cudaFuncAttributeMaxDynamicSharedMemorySize, SMEM);

    // 0) weight images + zero agg
    prep_kernel<<<5, 256>>>(mw1, uw1, uw2);
    {
        int n4 = NNODES * DD / 4;
        zero_kernel<<<(n4 + 255) / 256, 256>>>((float4*)agg, n4);
    }
    // 1) P = nodes @ mw1_top + mb1
    tgemm<true, false, false, false, false><<<NGRID, NTHREADS, SMEM>>>(
        nodes, Wimg + 0 * 65536, nullptr, mb1, nullptr, nullptr, P, NNODES);
    // 2) agg[dst] += silu(ef @ mw1_bot + P[src])
    tgemm<false, true, true, true, true><<<NGRID, NTHREADS, SMEM>>>(
        ef, Wimg + 1 * 65536, P, nullptr, ei, ei + NEDGES, agg, NEDGES);
    // 3) T = nodes @ uw1_top      (reuse g_P as T)
    tgemm<false, false, false, false, false><<<NGRID, NTHREADS, SMEM>>>(
        nodes, Wimg + 2 * 65536, nullptr, nullptr, nullptr, nullptr, P, NNODES);
    // 4) H = silu(agg @ uw1_bot + T + ub1)
    tgemm<true, true, false, true, false><<<NGRID, NTHREADS, SMEM>>>(
        agg, Wimg + 3 * 65536, P, ub1, nullptr, nullptr, H, NNODES);
    // 5) out = H @ uw2 + nodes + ub2
    tgemm<true, true, false, false, false><<<NGRID, NTHREADS, SMEM>>>(
        H, Wimg + 4 * 65536, nodes, ub2, nullptr, nullptr, out, NNODES);
}

// round 6
// speedup vs baseline: 3.6770x; 1.1090x over previous
#include <cuda_runtime.h>
#include <cuda_fp16.h>
#include <cstdint>

#define DD       128
#define NNODES   40000
#define NEDGES   640000
#define NSM      148
#define NTHREADS 128
#define TILE_M   64
#define NGRID    (4 * NSM)

// ---------------- global scratch ----------------
// Weight images: 5 matrices, each 32KB: 8 k-chunks x 4KB (128 rows x 16 k fp16).
// Row-permuted (permcol) for v4 epilogue.
__device__ __align__(16) char g_Wimg[5][32768];
__device__ float g_P[(size_t)NNODES * DD];
__device__ float g_agg[(size_t)NNODES * DD];
__device__ float g_H[(size_t)NNODES * DD];

// ---------------- layout helpers ----------------
// B image chunk: 128 rows x 16 k fp16 = 4KB; 16B slot per (row, k-half), XOR-swizzled.
__host__ __device__ __forceinline__ int img_offB(int c, int r, int h) {
    int i = 2 * r + h;
    i ^= (i >> 3) & 1;
    return c * 4096 + (i << 4);
}
// A image chunk: 64 rows x 16 k fp16 = 2KB.
__device__ __forceinline__ int img_offA(int c, int r, int h) {
    int i = 2 * r + h;
    i ^= (i >> 3) & 1;
    return c * 2048 + (i << 4);
}
// Column permutation: warp fragment col-pairs -> 4 consecutive physical columns.
__host__ __device__ __forceinline__ int permcol(int n) {
    int nf = (n >> 3) & 3, j = n & 7;
    return (n & ~31) | ((nf >> 1) << 4) | ((j >> 1) << 2) | ((nf & 1) << 1) | (j & 1);
}

__device__ __forceinline__ uint32_t smem_u32(const void* p) {
    uint32_t a;
    asm("{ .reg .u64 t; cvta.to.shared.u64 t, %1; cvt.u32.u64 %0, t; }" : "=r"(a) : "l"(p));
    return a;
}
__device__ __forceinline__ uint32_t ldm_addrB(uint32_t base, int c, int r16, int lane) {
    int r = r16 + ((lane >> 3) & 1) * 8 + (lane & 7);
    int h = lane >> 4;
    int i = 2 * r + h;
    i ^= (i >> 3) & 1;
    return base + c * 4096 + (i << 4);
}
__device__ __forceinline__ uint32_t ldm_addrA(uint32_t base, int c, int r16, int lane) {
    int r = r16 + ((lane >> 3) & 1) * 8 + (lane & 7);
    int h = lane >> 4;
    int i = 2 * r + h;
    i ^= (i >> 3) & 1;
    return base + c * 2048 + (i << 4);
}

#define LDM4(d, addr) \
    asm volatile("ldmatrix.sync.aligned.m8n8.x4.shared.b16 {%0,%1,%2,%3}, [%4];" \
                 : "=r"((d)[0]), "=r"((d)[1]), "=r"((d)[2]), "=r"((d)[3]) : "r"(addr))

#define MMA(d, a, b0, b1) \
    asm volatile("mma.sync.aligned.m16n8k16.row.col.f32.f16.f16.f32 " \
                 "{%0,%1,%2,%3}, {%4,%5,%6,%7}, {%8,%9}, {%0,%1,%2,%3};" \
                 : "+f"((d)[0]), "+f"((d)[1]), "+f"((d)[2]), "+f"((d)[3]) \
                 : "r"((a)[0]), "r"((a)[1]), "r"((a)[2]), "r"((a)[3]), "r"(b0), "r"(b1))

__device__ __forceinline__ float silu_f(float x) { return x / (1.0f + __expf(-x)); }

__device__ __forceinline__ void red_add_v4(float* p, float a, float b, float c, float d) {
    asm volatile("red.global.add.v4.f32 [%0], {%1, %2, %3, %4};"
                 :: "l"(p), "f"(a), "f"(b), "f"(c), "f"(d) : "memory");
}

__device__ __forceinline__ uint32_t pk_h2(__half a, __half b) {
    __half2 t = __halves2half2(a, b);
    return *(uint32_t*)&t;
}

// ---------------- prep: image-layout weights (single fp16) ----------------
__global__ void prep_kernel(const float* __restrict__ mw1, const float* __restrict__ uw1,
                            const float* __restrict__ uw2) {
    const int which = blockIdx.x;
    const float* W;
    switch (which) {
        case 0: W = mw1; break;
        case 1: W = mw1 + DD * DD; break;
        case 2: W = uw1; break;
        case 3: W = uw1 + DD * DD; break;
        default: W = uw2; break;
    }
    char* img = &g_Wimg[which][0];
    for (int i = threadIdx.x; i < DD * DD; i += blockDim.x) {
        int n = i >> 7, k = i & 127;
        float w = W[k * DD + permcol(n)];
        int c = k >> 4, kk = k & 15, h = kk >> 3, b = kk & 7;
        *(__half*)(img + img_offB(c, n, h) + b * 2) = __float2half_rn(w);
    }
}

__global__ void zero_kernel(float4* p, int n4) {
    int i = blockIdx.x * blockDim.x + threadIdx.x;
    if (i < n4) p[i] = make_float4(0.f, 0.f, 0.f, 0.f);
}

// ---------------- main GEMM kernel ----------------
// 64-row tiles, 128 threads (4 warps), warp tile 32x64 (wm = wid&1, wn = wid>>1).
// smem/CTA = 32KB B + 16KB A -> 4 CTAs/SM. Single-pass fp16.
template <bool BIAS, bool ADD, bool GATHER, bool SILU, bool SCATTER>
__global__ void __launch_bounds__(NTHREADS, 4)
tgemm(const float* __restrict__ A, const char* __restrict__ Bimg,
      const float* __restrict__ addv, const float* __restrict__ bias,
      const int* __restrict__ gsrc, const int* __restrict__ gdst,
      float* __restrict__ Out, int nrows) {
    extern __shared__ char sm[];          // [0,32K) B image, [32K,48K) A image
    __shared__ int s_idx[2 * TILE_M];
    const uint32_t Bs = smem_u32(sm);
    const uint32_t As = Bs + 32768;
    const int tid = threadIdx.x, lane = tid & 31, wid = tid >> 5;
    const int wm = wid & 1, wn = wid >> 1;   // rows wm*32+, cols wn*64+

    // load B image once (32KB)
    for (int i = tid; i < 2048; i += NTHREADS)
        ((uint4*)sm)[i] = __ldg((const uint4*)Bimg + i);

    // bias preload: 2 col-groups x 2 sub-groups
    float4 bias_r[2][2];
#pragma unroll
    for (int g = 0; g < 2; g++)
#pragma unroll
        for (int p = 0; p < 2; p++)
            bias_r[g][p] = BIAS
                ? __ldg((const float4*)(bias + wn * 64 + g * 32 + p * 16 + (lane & 3) * 4))
                : make_float4(0.f, 0.f, 0.f, 0.f);
    __syncthreads();

    const int tiles = (nrows + TILE_M - 1) / TILE_M;
    for (int tile = blockIdx.x; tile < tiles; tile += (int)gridDim.x) {
        const long rowbase = (long)tile * TILE_M;

        // ---- convert A tile: fp32 -> fp16 image in smem ----
        {
            const int r = tid >> 1;                // 0..63
            const int cseg = (tid & 1) << 6;       // 0 or 64
            const long gr = rowbase + r;
            const bool valid = gr < (long)nrows;
            const float4* srcp = (const float4*)(A + gr * DD + cseg);
#pragma unroll
            for (int j = 0; j < 8; j++) {
                float x[8];
                if (valid) {
                    float4 u = __ldg(srcp + 2 * j);
                    float4 v = __ldg(srcp + 2 * j + 1);
                    x[0] = u.x; x[1] = u.y; x[2] = u.z; x[3] = u.w;
                    x[4] = v.x; x[5] = v.y; x[6] = v.z; x[7] = v.w;
                } else {
#pragma unroll
                    for (int q = 0; q < 8; q++) x[q] = 0.f;
                }
                const int col0 = cseg + j * 8;
                const int c = col0 >> 4, h = (col0 >> 3) & 1;
                *(uint4*)(sm + 32768 + img_offA(c, r, h)) = make_uint4(
                    pk_h2(__float2half_rn(x[0]), __float2half_rn(x[1])),
                    pk_h2(__float2half_rn(x[2]), __float2half_rn(x[3])),
                    pk_h2(__float2half_rn(x[4]), __float2half_rn(x[5])),
                    pk_h2(__float2half_rn(x[6]), __float2half_rn(x[7])));
            }
        }
        if (GATHER && tid < TILE_M) {
            long gr = rowbase + tid;
            s_idx[tid] = (gr < (long)nrows) ? __ldg(gsrc + gr) : 0;
        }
        if (SCATTER && tid >= TILE_M) {
            int r2 = tid - TILE_M;
            long gr = rowbase + r2;
            s_idx[TILE_M + r2] = (gr < (long)nrows) ? __ldg(gdst + gr) : 0;
        }
        __syncthreads();

        // ---- MMA: acc = A*B over 8 k16-chunks ----
        float acc[2][8][4];
#pragma unroll
        for (int mf = 0; mf < 2; mf++)
#pragma unroll
            for (int nf = 0; nf < 8; nf++)
#pragma unroll
                for (int q = 0; q < 4; q++) acc[mf][nf][q] = 0.f;

#pragma unroll
        for (int c = 0; c < 8; c++) {
            uint32_t b[4][4], a[2][4];
#pragma unroll
            for (int g = 0; g < 4; g++)
                LDM4(b[g], ldm_addrB(Bs, c, wn * 64 + g * 16, lane));
#pragma unroll
            for (int mf = 0; mf < 2; mf++)
                LDM4(a[mf], ldm_addrA(As, c, wm * 32 + mf * 16, lane));

#pragma unroll
            for (int mf = 0; mf < 2; mf++)
#pragma unroll
                for (int nf = 0; nf < 8; nf++)
                    MMA(acc[mf][nf], a[mf], b[nf >> 1][nf & 1],
                        b[nf >> 1][(nf & 1) + 2]);
        }

        // ---- epilogue straight from registers ----
        {
            const int q = lane & 3, ro = lane >> 2;
#pragma unroll
            for (int mf = 0; mf < 2; mf++) {
#pragma unroll
                for (int rh = 0; rh < 2; rh++) {
                    const int r = wm * 32 + mf * 16 + rh * 8 + ro;
                    const long gr = rowbase + r;
                    if (gr >= (long)nrows) continue;
                    const long arow = GATHER ? (long)s_idx[r] : gr;
                    const long orow = SCATTER ? (long)s_idx[TILE_M + r] : gr;
#pragma unroll
                    for (int g = 0; g < 2; g++) {
#pragma unroll
                        for (int p = 0; p < 2; p++) {
                            const int cc = wn * 64 + g * 32 + p * 16 + q * 4;
                            const int nfb = g * 4 + 2 * p;
                            float v0 = acc[mf][nfb][2 * rh];
                            float v1 = acc[mf][nfb][2 * rh + 1];
                            float v2 = acc[mf][nfb + 1][2 * rh];
                            float v3 = acc[mf][nfb + 1][2 * rh + 1];
                            if (ADD) {
                                float4 t = __ldg((const float4*)(addv + arow * DD + cc));
                                v0 += t.x; v1 += t.y; v2 += t.z; v3 += t.w;
                            }
                            if (BIAS) {
                                float4 b = bias_r[g][p];
                                v0 += b.x; v1 += b.y; v2 += b.z; v3 += b.w;
                            }
                            if (SILU) {
                                v0 = silu_f(v0); v1 = silu_f(v1);
                                v2 = silu_f(v2); v3 = silu_f(v3);
                            }
                            float* op = Out + orow * DD + cc;
                            if (SCATTER) red_add_v4(op, v0, v1, v2, v3);
                            else *(float4*)op = make_float4(v0, v1, v2, v3);
                        }
                    }
                }
            }
        }
        __syncthreads();
    }
}

// ---------------- launch ----------------
extern "C" void kernel_launch(void* const* d_in, const int* in_sizes, int n_in,
                              void* d_out, int out_size) {
    const float* nodes = (const float*)d_in[0];
    const int*   ei    = (const int*)d_in[1];   // [2,E]: row0=src, row1=dst
    const float* ef    = (const float*)d_in[2];
    const float* mw1   = (const float*)d_in[3];
    const float* mb1   = (const float*)d_in[4];
    const float* uw1   = (const float*)d_in[5];
    const float* ub1   = (const float*)d_in[6];
    const float* uw2   = (const float*)d_in[7];
    const float* ub2   = (const float*)d_in[8];
    float* out = (float*)d_out;

    char* Wimg;
    float *P, *agg, *H;
    cudaGetSymbolAddress((void**)&Wimg, g_Wimg);
    cudaGetSymbolAddress((void**)&P,    g_P);
    cudaGetSymbolAddress((void**)&agg,  g_agg);
    cudaGetSymbolAddress((void**)&H,    g_H);

    const int SMEM = 49152;   // 32KB B + 16KB A
    cudaFuncSetAttribute(tgemm<true,  false, false, false, false>,
                         cudaFuncAttributeMaxDynamicSharedMemorySize, SMEM);
    cudaFuncSetAttribute(tgemm<false, true,  true,  true,  true>,
                         cudaFuncAttributeMaxDynamicSharedMemorySize, SMEM);
    cudaFuncSetAttribute(tgemm<false, false, false, false, false>,
                         cudaFuncAttributeMaxDynamicSharedMemorySize, SMEM);
    cudaFuncSetAttribute(tgemm<true,  true,  false, true,  false>,
                         cudaFuncAttributeMaxDynamicSharedMemorySize, SMEM);
    cudaFuncSetAttribute(tgemm<true,  true,  false, false, false>,
                         cudaFuncAttributeMaxDynamicSharedMemorySize, SMEM);

    // 0) weight images + zero agg
    prep_kernel<<<5, 256>>>(mw1, uw1, uw2);
    {
        int n4 = NNODES * DD / 4;
        zero_kernel<<<(n4 + 255) / 256, 256>>>((float4*)agg, n4);
    }
    // 1) P = nodes @ mw1_top + mb1
    tgemm<true, false, false, false, false><<<NGRID, NTHREADS, SMEM>>>(
        nodes, Wimg + 0 * 32768, nullptr, mb1, nullptr, nullptr, P, NNODES);
    // 2) agg[dst] += silu(ef @ mw1_bot + P[src])
    tgemm<false, true, true, true, true><<<NGRID, NTHREADS, SMEM>>>(
        ef, Wimg + 1 * 32768, P, nullptr, ei, ei + NEDGES, agg, NEDGES);
    // 3) T = nodes @ uw1_top      (reuse g_P as T)
    tgemm<false, false, false, false, false><<<NGRID, NTHREADS, SMEM>>>(
        nodes, Wimg + 2 * 32768, nullptr, nullptr, nullptr, nullptr, P, NNODES);
    // 4) H = silu(agg @ uw1_bot + T + ub1)
    tgemm<true, true, false, true, false><<<NGRID, NTHREADS, SMEM>>>(
        agg, Wimg + 3 * 32768, P, ub1, nullptr, nullptr, H, NNODES);
    // 5) out = H @ uw2 + nodes + ub2
    tgemm<true, true, false, false, false><<<NGRID, NTHREADS, SMEM>>>(
        H, Wimg + 4 * 32768, nodes, ub2, nullptr, nullptr, out, NNODES);
}

// round 7
// speedup vs baseline: 4.4310x; 1.2051x over previous
#include <cuda_runtime.h>
#include <cuda_fp16.h>
#include <cstdint>

#define DD       128
#define NNODES   40000
#define NEDGES   640000
#define NTHREADS 128
#define TILE_M   32
#define NGRID    592

// ---------------- global scratch ----------------
// B fragment images: per matrix, u32[ (wn*8 + c)*32*8 + lane*8 + j ]:
// j = nf*2 + h; value = fp16x2 { W[k, permcol(n)], W[k+1, permcol(n)] },
// n = wn*32 + nf*8 + (lane>>2), k = c*16 + h*8 + (lane&3)*2.
__device__ __align__(16) unsigned g_Bfrag[5][8192];
__device__ float g_P[(size_t)NNODES * DD];
__device__ float g_agg[(size_t)NNODES * DD];
__device__ float g_H[(size_t)NNODES * DD];

// ---------------- helpers ----------------
// Column permutation: warp fragment col-pairs -> 4 consecutive physical columns.
__host__ __device__ __forceinline__ int permcol(int n) {
    int nf = (n >> 3) & 3, j = n & 7;
    return (n & ~31) | ((nf >> 1) << 4) | ((j >> 1) << 2) | ((nf & 1) << 1) | (j & 1);
}
// A image: 8 chunks x 1KB (32 rows x 16 k fp16); 16B slot per (row, k-half), swizzled.
__device__ __forceinline__ int img_offA(int c, int r, int h) {
    int i = 2 * r + h;
    i ^= (i >> 3) & 1;
    return c * 1024 + (i << 4);
}
__device__ __forceinline__ uint32_t smem_u32(const void* p) {
    uint32_t a;
    asm("{ .reg .u64 t; cvta.to.shared.u64 t, %1; cvt.u32.u64 %0, t; }" : "=r"(a) : "l"(p));
    return a;
}
__device__ __forceinline__ uint32_t ldm_addrA(uint32_t base, int c, int mf, int lane) {
    int r = mf * 16 + ((lane >> 3) & 1) * 8 + (lane & 7);
    int h = lane >> 4;
    int i = 2 * r + h;
    i ^= (i >> 3) & 1;
    return base + c * 1024 + (i << 4);
}

#define LDM4(d, addr) \
    asm volatile("ldmatrix.sync.aligned.m8n8.x4.shared.b16 {%0,%1,%2,%3}, [%4];" \
                 : "=r"((d)[0]), "=r"((d)[1]), "=r"((d)[2]), "=r"((d)[3]) : "r"(addr))

#define MMA(d, a, b0, b1) \
    asm volatile("mma.sync.aligned.m16n8k16.row.col.f32.f16.f16.f32 " \
                 "{%0,%1,%2,%3}, {%4,%5,%6,%7}, {%8,%9}, {%0,%1,%2,%3};" \
                 : "+f"((d)[0]), "+f"((d)[1]), "+f"((d)[2]), "+f"((d)[3]) \
                 : "r"((a)[0]), "r"((a)[1]), "r"((a)[2]), "r"((a)[3]), "r"(b0), "r"(b1))

__device__ __forceinline__ float silu_f(float x) { return x / (1.0f + __expf(-x)); }

__device__ __forceinline__ void red_add_v4(float* p, float a, float b, float c, float d) {
    asm volatile("red.global.add.v4.f32 [%0], {%1, %2, %3, %4};"
                 :: "l"(p), "f"(a), "f"(b), "f"(c), "f"(d) : "memory");
}

__device__ __forceinline__ uint32_t pk_h2(__half a, __half b) {
    __half2 t = __halves2half2(a, b);
    return *(uint32_t*)&t;
}

// ---------------- prep: B fragment images ----------------
__global__ void prep_kernel(const float* __restrict__ mw1, const float* __restrict__ uw1,
                            const float* __restrict__ uw2) {
    const int which = blockIdx.x;
    const float* W;
    switch (which) {
        case 0: W = mw1; break;
        case 1: W = mw1 + DD * DD; break;
        case 2: W = uw1; break;
        case 3: W = uw1 + DD * DD; break;
        default: W = uw2; break;
    }
    unsigned* dst = &g_Bfrag[which][0];
    for (int e = threadIdx.x; e < 8192; e += blockDim.x) {
        int wn = e >> 11, c = (e >> 8) & 7, lane = (e >> 3) & 31, j = e & 7;
        int nf = j >> 1, h = j & 1;
        int n = wn * 32 + nf * 8 + (lane >> 2);
        int col = permcol(n);
        int k = c * 16 + h * 8 + (lane & 3) * 2;
        dst[e] = pk_h2(__float2half_rn(W[k * DD + col]),
                       __float2half_rn(W[(k + 1) * DD + col]));
    }
}

__global__ void zero_kernel(float4* p, int n4) {
    int i = blockIdx.x * blockDim.x + threadIdx.x;
    if (i < n4) p[i] = make_float4(0.f, 0.f, 0.f, 0.f);
}

// ---------------- A tile convert: fp32 -> fp16 image ----------------
// warp w handles cols w*32..+31, lane = row. STS phases conflict-free.
__device__ __forceinline__ void convertA(char* buf, const float* __restrict__ A,
                                         long rowbase) {
    const int r = threadIdx.x & 31;
    const int cseg = (threadIdx.x >> 5) << 5;
    const float4* srcp = (const float4*)(A + (rowbase + r) * DD + cseg);
#pragma unroll
    for (int j = 0; j < 4; j++) {
        float4 u = __ldg(srcp + 2 * j);
        float4 v = __ldg(srcp + 2 * j + 1);
        const int col0 = cseg + j * 8;
        const int c = col0 >> 4, h = (col0 >> 3) & 1;
        *(uint4*)(buf + img_offA(c, r, h)) = make_uint4(
            pk_h2(__float2half_rn(u.x), __float2half_rn(u.y)),
            pk_h2(__float2half_rn(u.z), __float2half_rn(u.w)),
            pk_h2(__float2half_rn(v.x), __float2half_rn(v.y)),
            pk_h2(__float2half_rn(v.z), __float2half_rn(v.w)));
    }
}

// ---------------- main GEMM kernel ----------------
// 32-row tiles, 128 threads; warp wn owns cols wn*32..+31, all 32 rows.
// B panel register-resident (64 regs). A double-buffered in smem (2 x 8KB).
// One __syncthreads per tile; next-tile convert overlaps epilogue latency.
template <bool BIAS, bool ADD, bool GATHER, bool SILU, bool SCATTER>
__global__ void __launch_bounds__(NTHREADS, 4)
tgemm(const float* __restrict__ A, const unsigned* __restrict__ Bf,
      const float* __restrict__ addv, const float* __restrict__ bias,
      const int* __restrict__ gsrc, const int* __restrict__ gdst,
      float* __restrict__ Out, int nrows) {
    extern __shared__ char sm[];                 // 2 x 8KB A image buffers
    __shared__ int s_src[2][TILE_M];
    __shared__ int s_dst[2][TILE_M];
    const uint32_t As = smem_u32(sm);
    const int tid = threadIdx.x, lane = tid & 31, wn = tid >> 5;

    // ---- load this warp's B panel into registers (once) ----
    uint32_t bf[8][8];
    {
        const uint4* bp = (const uint4*)Bf;
#pragma unroll
        for (int c = 0; c < 8; c++) {
            const int base = ((wn * 8 + c) * 32 + lane) * 2;
            uint4 u0 = __ldg(bp + base);
            uint4 u1 = __ldg(bp + base + 1);
            bf[c][0] = u0.x; bf[c][1] = u0.y; bf[c][2] = u0.z; bf[c][3] = u0.w;
            bf[c][4] = u1.x; bf[c][5] = u1.y; bf[c][6] = u1.z; bf[c][7] = u1.w;
        }
    }
    // bias preload
    float4 bias_r[2];
#pragma unroll
    for (int p = 0; p < 2; p++)
        bias_r[p] = BIAS
            ? __ldg((const float4*)(bias + wn * 32 + p * 16 + (lane & 3) * 4))
            : make_float4(0.f, 0.f, 0.f, 0.f);

    const int tiles = nrows / TILE_M;            // nrows % 32 == 0 for this problem
    const int bid = blockIdx.x;
    if (bid >= tiles) return;
    const int ntb = (tiles - 1 - bid) / (int)gridDim.x + 1;

    // ---- prologue: stage tile 0 ----
    convertA(sm, A, (long)bid * TILE_M);
    if (GATHER && tid < TILE_M)
        s_src[0][tid] = __ldg(gsrc + (long)bid * TILE_M + tid);
    if (SCATTER && tid >= TILE_M && tid < 2 * TILE_M)
        s_dst[0][tid - TILE_M] = __ldg(gdst + (long)bid * TILE_M + (tid - TILE_M));

    for (int it = 0; it < ntb; it++) {
        const long tile = (long)bid + (long)it * gridDim.x;
        const long rowbase = tile * TILE_M;
        const int pb = it & 1;
        __syncthreads();

        // ---- MMA: 8 k16-chunks, A from smem, B from registers ----
        float acc[2][4][4];
#pragma unroll
        for (int mf = 0; mf < 2; mf++)
#pragma unroll
            for (int nf = 0; nf < 4; nf++)
#pragma unroll
                for (int q = 0; q < 4; q++) acc[mf][nf][q] = 0.f;

        const uint32_t Ab = As + pb * 8192;
#pragma unroll
        for (int c = 0; c < 8; c++) {
            uint32_t a[2][4];
            LDM4(a[0], ldm_addrA(Ab, c, 0, lane));
            LDM4(a[1], ldm_addrA(Ab, c, 1, lane));
#pragma unroll
            for (int mf = 0; mf < 2; mf++)
#pragma unroll
                for (int nf = 0; nf < 4; nf++)
                    MMA(acc[mf][nf], a[mf], bf[c][2 * nf], bf[c][2 * nf + 1]);
        }

        // ---- stage next tile (overlaps epilogue latency) ----
        if (it + 1 < ntb) {
            const long nt = tile + gridDim.x;
            convertA(sm + (pb ^ 1) * 8192, A, nt * TILE_M);
            if (GATHER && tid < TILE_M)
                s_src[pb ^ 1][tid] = __ldg(gsrc + nt * TILE_M + tid);
            if (SCATTER && tid >= TILE_M && tid < 2 * TILE_M)
                s_dst[pb ^ 1][tid - TILE_M] = __ldg(gdst + nt * TILE_M + (tid - TILE_M));
        }

        // ---- epilogue straight from registers ----
        {
            const int q = lane & 3, ro = lane >> 2;
#pragma unroll
            for (int mf = 0; mf < 2; mf++) {
#pragma unroll
                for (int rh = 0; rh < 2; rh++) {
                    const int r = mf * 16 + rh * 8 + ro;
                    const long gr = rowbase + r;
                    const long arow = GATHER ? (long)s_src[pb][r] : gr;
                    const long orow = SCATTER ? (long)s_dst[pb][r] : gr;
#pragma unroll
                    for (int p = 0; p < 2; p++) {
                        const int cc = wn * 32 + p * 16 + q * 4;
                        float v0 = acc[mf][2 * p][2 * rh];
                        float v1 = acc[mf][2 * p][2 * rh + 1];
                        float v2 = acc[mf][2 * p + 1][2 * rh];
                        float v3 = acc[mf][2 * p + 1][2 * rh + 1];
                        if (ADD) {
                            float4 t = __ldg((const float4*)(addv + arow * DD + cc));
                            v0 += t.x; v1 += t.y; v2 += t.z; v3 += t.w;
                        }
                        if (BIAS) {
                            float4 b = bias_r[p];
                            v0 += b.x; v1 += b.y; v2 += b.z; v3 += b.w;
                        }
                        if (SILU) {
                            v0 = silu_f(v0); v1 = silu_f(v1);
                            v2 = silu_f(v2); v3 = silu_f(v3);
                        }
                        float* op = Out + orow * DD + cc;
                        if (SCATTER) red_add_v4(op, v0, v1, v2, v3);
                        else *(float4*)op = make_float4(v0, v1, v2, v3);
                    }
                }
            }
        }
    }
}

// ---------------- launch ----------------
extern "C" void kernel_launch(void* const* d_in, const int* in_sizes, int n_in,
                              void* d_out, int out_size) {
    const float* nodes = (const float*)d_in[0];
    const int*   ei    = (const int*)d_in[1];   // [2,E]: row0=src, row1=dst
    const float* ef    = (const float*)d_in[2];
    const float* mw1   = (const float*)d_in[3];
    const float* mb1   = (const float*)d_in[4];
    const float* uw1   = (const float*)d_in[5];
    const float* ub1   = (const float*)d_in[6];
    const float* uw2   = (const float*)d_in[7];
    const float* ub2   = (const float*)d_in[8];
    float* out = (float*)d_out;

    unsigned* Bf;
    float *P, *agg, *H;
    cudaGetSymbolAddress((void**)&Bf,  g_Bfrag);
    cudaGetSymbolAddress((void**)&P,   g_P);
    cudaGetSymbolAddress((void**)&agg, g_agg);
    cudaGetSymbolAddress((void**)&H,   g_H);

    const int SMEM = 16384;   // 2 x 8KB A buffers

    // 0) B fragment images + zero agg
    prep_kernel<<<5, 256>>>(mw1, uw1, uw2);
    {
        int n4 = NNODES * DD / 4;
        zero_kernel<<<(n4 + 255) / 256, 256>>>((float4*)agg, n4);
    }
    // 1) P = nodes @ mw1_top + mb1
    tgemm<true, false, false, false, false><<<NGRID, NTHREADS, SMEM>>>(
        nodes, Bf + 0 * 8192, nullptr, mb1, nullptr, nullptr, P, NNODES);
    // 2) agg[dst] += silu(ef @ mw1_bot + P[src])
    tgemm<false, true, true, true, true><<<NGRID, NTHREADS, SMEM>>>(
        ef, Bf + 1 * 8192, P, nullptr, ei, ei + NEDGES, agg, NEDGES);
    // 3) T = nodes @ uw1_top      (reuse g_P as T)
    tgemm<false, false, false, false, false><<<NGRID, NTHREADS, SMEM>>>(
        nodes, Bf + 2 * 8192, nullptr, nullptr, nullptr, nullptr, P, NNODES);
    // 4) H = silu(agg @ uw1_bot + T + ub1)
    tgemm<true, true, false, true, false><<<NGRID, NTHREADS, SMEM>>>(
        agg, Bf + 3 * 8192, P, ub1, nullptr, nullptr, H, NNODES);
    // 5) out = H @ uw2 + nodes + ub2
    tgemm<true, true, false, false, false><<<NGRID, NTHREADS, SMEM>>>(
        H, Bf + 4 * 8192, nodes, ub2, nullptr, nullptr, out, NNODES);
}

// round 8
// speedup vs baseline: 4.5176x; 1.0196x over previous
#include <cuda_runtime.h>
#include <cuda_fp16.h>
#include <cstdint>

#define DD       128
#define NNODES   40000
#define NEDGES   640000
#define NTHREADS 128
#define TILE_M   32
#define NGRID    592

// smem layout (dynamic): [0,16K) A image double buffer, [16K,48K) gather staging x2
#define SM_A0    0
#define SM_STG   16384
#define SMEM_GEMM  16384
#define SMEM_EDGE  49152

// ---------------- global scratch ----------------
// B fragment images: per matrix, u32[(wn*8 + c)*32*8 + lane*8 + j]
__device__ __align__(16) unsigned g_Bfrag[5][8192];
__device__ float g_P[(size_t)NNODES * DD];
__device__ float g_agg[(size_t)NNODES * DD];
__device__ float g_H[(size_t)NNODES * DD];

// ---------------- helpers ----------------
__host__ __device__ __forceinline__ int permcol(int n) {
    int nf = (n >> 3) & 3, j = n & 7;
    return (n & ~31) | ((nf >> 1) << 4) | ((j >> 1) << 2) | ((nf & 1) << 1) | (j & 1);
}
__device__ __forceinline__ int img_offA(int c, int r, int h) {
    int i = 2 * r + h;
    i ^= (i >> 3) & 1;
    return c * 1024 + (i << 4);
}
__device__ __forceinline__ uint32_t smem_u32(const void* p) {
    uint32_t a;
    asm("{ .reg .u64 t; cvta.to.shared.u64 t, %1; cvt.u32.u64 %0, t; }" : "=r"(a) : "l"(p));
    return a;
}
__device__ __forceinline__ uint32_t ldm_addrA(uint32_t base, int c, int mf, int lane) {
    int r = mf * 16 + ((lane >> 3) & 1) * 8 + (lane & 7);
    int h = lane >> 4;
    int i = 2 * r + h;
    i ^= (i >> 3) & 1;
    return base + c * 1024 + (i << 4);
}

#define LDM4(d, addr) \
    asm volatile("ldmatrix.sync.aligned.m8n8.x4.shared.b16 {%0,%1,%2,%3}, [%4];" \
                 : "=r"((d)[0]), "=r"((d)[1]), "=r"((d)[2]), "=r"((d)[3]) : "r"(addr))

#define MMA(d, a, b0, b1) \
    asm volatile("mma.sync.aligned.m16n8k16.row.col.f32.f16.f16.f32 " \
                 "{%0,%1,%2,%3}, {%4,%5,%6,%7}, {%8,%9}, {%0,%1,%2,%3};" \
                 : "+f"((d)[0]), "+f"((d)[1]), "+f"((d)[2]), "+f"((d)[3]) \
                 : "r"((a)[0]), "r"((a)[1]), "r"((a)[2]), "r"((a)[3]), "r"(b0), "r"(b1))

#define CP_ASYNC16(dst, src) \
    asm volatile("cp.async.cg.shared.global [%0], [%1], 16;" :: "r"(dst), "l"(src))
#define CP_COMMIT() asm volatile("cp.async.commit_group;" ::: "memory")
#define CP_WAIT0()  asm volatile("cp.async.wait_group 0;" ::: "memory")

__device__ __forceinline__ float silu_f(float x) { return x / (1.0f + __expf(-x)); }

__device__ __forceinline__ void red_add_v4(float* p, float a, float b, float c, float d) {
    asm volatile("red.global.add.v4.f32 [%0], {%1, %2, %3, %4};"
                 :: "l"(p), "f"(a), "f"(b), "f"(c), "f"(d) : "memory");
}

__device__ __forceinline__ uint32_t pk_h2(__half a, __half b) {
    __half2 t = __halves2half2(a, b);
    return *(uint32_t*)&t;
}

// ---------------- prep: B fragment images ----------------
__global__ void prep_kernel(const float* __restrict__ mw1, const float* __restrict__ uw1,
                            const float* __restrict__ uw2) {
    const int which = blockIdx.x;
    const float* W;
    switch (which) {
        case 0: W = mw1; break;
        case 1: W = mw1 + DD * DD; break;
        case 2: W = uw1; break;
        case 3: W = uw1 + DD * DD; break;
        default: W = uw2; break;
    }
    unsigned* dst = &g_Bfrag[which][0];
    for (int e = threadIdx.x; e < 8192; e += blockDim.x) {
        int wn = e >> 11, c = (e >> 8) & 7, lane = (e >> 3) & 31, j = e & 7;
        int nf = j >> 1, h = j & 1;
        int n = wn * 32 + nf * 8 + (lane >> 2);
        int col = permcol(n);
        int k = c * 16 + h * 8 + (lane & 3) * 2;
        dst[e] = pk_h2(__float2half_rn(W[k * DD + col]),
                       __float2half_rn(W[(k + 1) * DD + col]));
    }
}

__global__ void zero_kernel(float4* p, int n4) {
    int i = blockIdx.x * blockDim.x + threadIdx.x;
    if (i < n4) p[i] = make_float4(0.f, 0.f, 0.f, 0.f);
}

// ---------------- A tile convert: fp32 -> fp16 image ----------------
__device__ __forceinline__ void convertA(char* buf, const float* __restrict__ A,
                                         long rowbase) {
    const int r = threadIdx.x & 31;
    const int cseg = (threadIdx.x >> 5) << 5;
    const float4* srcp = (const float4*)(A + (rowbase + r) * DD + cseg);
#pragma unroll
    for (int j = 0; j < 4; j++) {
        float4 u = __ldg(srcp + 2 * j);
        float4 v = __ldg(srcp + 2 * j + 1);
        const int col0 = cseg + j * 8;
        const int c = col0 >> 4, h = (col0 >> 3) & 1;
        *(uint4*)(buf + img_offA(c, r, h)) = make_uint4(
            pk_h2(__float2half_rn(u.x), __float2half_rn(u.y)),
            pk_h2(__float2half_rn(u.z), __float2half_rn(u.w)),
            pk_h2(__float2half_rn(v.x), __float2half_rn(v.y)),
            pk_h2(__float2half_rn(v.z), __float2half_rn(v.w)));
    }
}

// ---------------- main GEMM kernel ----------------
// 32-row tiles, 128 threads; warp wn owns cols wn*32..+31.
// B register-resident; A double-buffered; GATHER rows staged via cp.async.cg.
template <bool BIAS, bool ADD, bool GATHER, bool SILU, bool SCATTER>
__global__ void __launch_bounds__(NTHREADS, 4)
tgemm(const float* __restrict__ A, const unsigned* __restrict__ Bf,
      const float* __restrict__ addv, const float* __restrict__ bias,
      const int* __restrict__ gsrc, const int* __restrict__ gdst,
      float* __restrict__ Out, int nrows) {
    extern __shared__ char sm[];
    __shared__ int s_dst[2][TILE_M];
    const uint32_t As = smem_u32(sm);
    const int tid = threadIdx.x, lane = tid & 31, wn = tid >> 5;

    // staging writer mapping (GATHER): thread stages row srow, 128B quarter qseg
    const int srow = tid >> 2;
    const int qseg = (tid & 3) << 3;     // chunk base (16B chunks): 0,8,16,24

    // ---- load this warp's B panel into registers (once) ----
    uint32_t bf[8][8];
    {
        const uint4* bp = (const uint4*)Bf;
#pragma unroll
        for (int c = 0; c < 8; c++) {
            const int base = ((wn * 8 + c) * 32 + lane) * 2;
            uint4 u0 = __ldg(bp + base);
            uint4 u1 = __ldg(bp + base + 1);
            bf[c][0] = u0.x; bf[c][1] = u0.y; bf[c][2] = u0.z; bf[c][3] = u0.w;
            bf[c][4] = u1.x; bf[c][5] = u1.y; bf[c][6] = u1.z; bf[c][7] = u1.w;
        }
    }
    float4 bias_r[2];
#pragma unroll
    for (int p = 0; p < 2; p++)
        bias_r[p] = BIAS
            ? __ldg((const float4*)(bias + wn * 32 + p * 16 + (lane & 3) * 4))
            : make_float4(0.f, 0.f, 0.f, 0.f);

    const int tiles = nrows / TILE_M;    // divisible for this problem
    const int bid = blockIdx.x;
    if (bid >= tiles) return;
    const int ntb = (tiles - 1 - bid) / (int)gridDim.x + 1;

    // ---- prologue: stage tile 0; prefetch idx for tile 1 ----
    convertA(sm + SM_A0, A, (long)bid * TILE_M);
    int idx_next = 0;
    if (GATHER) {
        int idx0 = __ldg(gsrc + (long)bid * TILE_M + srow);
        const float* gp = addv + (size_t)idx0 * DD;
        uint32_t sd = As + SM_STG + srow * 512;
#pragma unroll
        for (int i = 0; i < 8; i++) {
            int ch = qseg + i;
            CP_ASYNC16(sd + ((ch ^ (srow & 7)) << 4), gp + ch * 4);
        }
        CP_COMMIT();
        if (ntb > 1)
            idx_next = __ldg(gsrc + ((long)bid + gridDim.x) * TILE_M + srow);
    }
    if (SCATTER && tid >= TILE_M && tid < 2 * TILE_M)
        s_dst[0][tid - TILE_M] = __ldg(gdst + (long)bid * TILE_M + (tid - TILE_M));

    for (int it = 0; it < ntb; it++) {
        const long tile = (long)bid + (long)it * gridDim.x;
        const long rowbase = tile * TILE_M;
        const int pb = it & 1;
        if (GATHER) CP_WAIT0();
        __syncthreads();

        // ---- MMA: 8 k16-chunks, A from smem, B from registers ----
        float acc[2][4][4];
#pragma unroll
        for (int mf = 0; mf < 2; mf++)
#pragma unroll
            for (int nf = 0; nf < 4; nf++)
#pragma unroll
                for (int q = 0; q < 4; q++) acc[mf][nf][q] = 0.f;

        const uint32_t Ab = As + SM_A0 + pb * 8192;
#pragma unroll
        for (int c = 0; c < 8; c++) {
            uint32_t a[2][4];
            LDM4(a[0], ldm_addrA(Ab, c, 0, lane));
            LDM4(a[1], ldm_addrA(Ab, c, 1, lane));
#pragma unroll
            for (int mf = 0; mf < 2; mf++)
#pragma unroll
                for (int nf = 0; nf < 4; nf++)
                    MMA(acc[mf][nf], a[mf], bf[c][2 * nf], bf[c][2 * nf + 1]);
        }

        // ---- stage next tile (overlaps epilogue) ----
        if (it + 1 < ntb) {
            const long nt = tile + gridDim.x;
            convertA(sm + SM_A0 + (pb ^ 1) * 8192, A, nt * TILE_M);
            if (GATHER) {
                const float* gp = addv + (size_t)idx_next * DD;
                uint32_t sd = As + SM_STG + (pb ^ 1) * 16384 + srow * 512;
#pragma unroll
                for (int i = 0; i < 8; i++) {
                    int ch = qseg + i;
                    CP_ASYNC16(sd + ((ch ^ (srow & 7)) << 4), gp + ch * 4);
                }
                CP_COMMIT();
                if (it + 2 < ntb)
                    idx_next = __ldg(gsrc + (nt + gridDim.x) * TILE_M + srow);
            }
            if (SCATTER && tid >= TILE_M && tid < 2 * TILE_M)
                s_dst[pb ^ 1][tid - TILE_M] = __ldg(gdst + nt * TILE_M + (tid - TILE_M));
        }

        // ---- epilogue straight from registers ----
        {
            const int q = lane & 3, ro = lane >> 2;
            const char* stg = sm + SM_STG + pb * 16384;
#pragma unroll
            for (int mf = 0; mf < 2; mf++) {
#pragma unroll
                for (int rh = 0; rh < 2; rh++) {
                    const int r = mf * 16 + rh * 8 + ro;
                    const long gr = rowbase + r;
                    const long orow = SCATTER ? (long)s_dst[pb][r] : gr;
#pragma unroll
                    for (int p = 0; p < 2; p++) {
                        const int cc = wn * 32 + p * 16 + q * 4;
                        float v0 = acc[mf][2 * p][2 * rh];
                        float v1 = acc[mf][2 * p][2 * rh + 1];
                        float v2 = acc[mf][2 * p + 1][2 * rh];
                        float v3 = acc[mf][2 * p + 1][2 * rh + 1];
                        if (ADD) {
                            float4 t;
                            if (GATHER) {
                                const int ch = wn * 8 + p * 4 + q;
                                t = *(const float4*)(stg + r * 512 +
                                                     ((ch ^ (r & 7)) << 4));
                            } else {
                                t = __ldg((const float4*)(addv + gr * DD + cc));
                            }
                            v0 += t.x; v1 += t.y; v2 += t.z; v3 += t.w;
                        }
                        if (BIAS) {
                            float4 b = bias_r[p];
                            v0 += b.x; v1 += b.y; v2 += b.z; v3 += b.w;
                        }
                        if (SILU) {
                            v0 = silu_f(v0); v1 = silu_f(v1);
                            v2 = silu_f(v2); v3 = silu_f(v3);
                        }
                        float* op = Out + orow * DD + cc;
                        if (SCATTER) red_add_v4(op, v0, v1, v2, v3);
                        else *(float4*)op = make_float4(v0, v1, v2, v3);
                    }
                }
            }
        }
    }
}

// ---------------- launch ----------------
extern "C" void kernel_launch(void* const* d_in, const int* in_sizes, int n_in,
                              void* d_out, int out_size) {
    const float* nodes = (const float*)d_in[0];
    const int*   ei    = (const int*)d_in[1];   // [2,E]: row0=src, row1=dst
    const float* ef    = (const float*)d_in[2];
    const float* mw1   = (const float*)d_in[3];
    const float* mb1   = (const float*)d_in[4];
    const float* uw1   = (const float*)d_in[5];
    const float* ub1   = (const float*)d_in[6];
    const float* uw2   = (const float*)d_in[7];
    const float* ub2   = (const float*)d_in[8];
    float* out = (float*)d_out;

    unsigned* Bf;
    float *P, *agg, *H;
    cudaGetSymbolAddress((void**)&Bf,  g_Bfrag);
    cudaGetSymbolAddress((void**)&P,   g_P);
    cudaGetSymbolAddress((void**)&agg, g_agg);
    cudaGetSymbolAddress((void**)&H,   g_H);

    cudaFuncSetAttribute(tgemm<false, true, true, true, true>,
                         cudaFuncAttributeMaxDynamicSharedMemorySize, SMEM_EDGE);

    // 0) B fragment images + zero agg
    prep_kernel<<<5, 256>>>(mw1, uw1, uw2);
    {
        int n4 = NNODES * DD / 4;
        zero_kernel<<<(n4 + 255) / 256, 256>>>((float4*)agg, n4);
    }
    // 1) P = nodes @ mw1_top + mb1
    tgemm<true, false, false, false, false><<<NGRID, NTHREADS, SMEM_GEMM>>>(
        nodes, Bf + 0 * 8192, nullptr, mb1, nullptr, nullptr, P, NNODES);
    // 2) agg[dst] += silu(ef @ mw1_bot + P[src])
    tgemm<false, true, true, true, true><<<NGRID, NTHREADS, SMEM_EDGE>>>(
        ef, Bf + 1 * 8192, P, nullptr, ei, ei + NEDGES, agg, NEDGES);
    // 3) T = nodes @ uw1_top      (reuse g_P as T)
    tgemm<false, false, false, false, false><<<NGRID, NTHREADS, SMEM_GEMM>>>(
        nodes, Bf + 2 * 8192, nullptr, nullptr, nullptr, nullptr, P, NNODES);
    // 4) H = silu(agg @ uw1_bot + T + ub1)
    tgemm<true, true, false, true, false><<<NGRID, NTHREADS, SMEM_GEMM>>>(
        agg, Bf + 3 * 8192, P, ub1, nullptr, nullptr, H, NNODES);
    // 5) out = H @ uw2 + nodes + ub2
    tgemm<true, true, false, false, false><<<NGRID, NTHREADS, SMEM_GEMM>>>(
        H, Bf + 4 * 8192, nodes, ub2, nullptr, nullptr, out, NNODES);
}

// round 9
// speedup vs baseline: 4.8696x; 1.0779x over previous
#include <cuda_runtime.h>
#include <cuda_fp16.h>
#include <cstdint>

#define DD       128
#define NNODES   40000
#define NEDGES   640000
#define NTHREADS 128
#define TILE_M   32
#define NGRID    592

// edge smem: [0,16K) A image x2, [16K,48K) gather staging x2
#define SM_STG     16384
#define SMEM_GEMM  16384
#define SMEM_EDGE  49152
// fused smem: [0,8K) A1/H image, [8K,16K) A2 image, [16K,48K) B2 panels, [48K,80K) B3
#define FB2        16384
#define FB3        49152
#define SMEM_FUSED 81920

// ---------------- global scratch ----------------
// B fragment images: per matrix, u32[(wn*8 + c)*32*8 + lane*8 + j]
__device__ __align__(16) unsigned g_Bfrag[5][8192];
__device__ float g_P[(size_t)NNODES * DD];
__device__ float g_agg[(size_t)NNODES * DD];

// ---------------- helpers ----------------
__host__ __device__ __forceinline__ int permcol(int n) {
    int nf = (n >> 3) & 3, j = n & 7;
    return (n & ~31) | ((nf >> 1) << 4) | ((j >> 1) << 2) | ((nf & 1) << 1) | (j & 1);
}
__device__ __forceinline__ int img_offA(int c, int r, int h) {
    int i = 2 * r + h;
    i ^= (i >> 3) & 1;
    return c * 1024 + (i << 4);
}
__device__ __forceinline__ uint32_t smem_u32(const void* p) {
    uint32_t a;
    asm("{ .reg .u64 t; cvta.to.shared.u64 t, %1; cvt.u32.u64 %0, t; }" : "=r"(a) : "l"(p));
    return a;
}
__device__ __forceinline__ uint32_t ldm_addrA(uint32_t base, int c, int mf, int lane) {
    int r = mf * 16 + ((lane >> 3) & 1) * 8 + (lane & 7);
    int h = lane >> 4;
    int i = 2 * r + h;
    i ^= (i >> 3) & 1;
    return base + c * 1024 + (i << 4);
}

#define LDM4(d, addr) \
    asm volatile("ldmatrix.sync.aligned.m8n8.x4.shared.b16 {%0,%1,%2,%3}, [%4];" \
                 : "=r"((d)[0]), "=r"((d)[1]), "=r"((d)[2]), "=r"((d)[3]) : "r"(addr))

#define MMA(d, a, b0, b1) \
    asm volatile("mma.sync.aligned.m16n8k16.row.col.f32.f16.f16.f32 " \
                 "{%0,%1,%2,%3}, {%4,%5,%6,%7}, {%8,%9}, {%0,%1,%2,%3};" \
                 : "+f"((d)[0]), "+f"((d)[1]), "+f"((d)[2]), "+f"((d)[3]) \
                 : "r"((a)[0]), "r"((a)[1]), "r"((a)[2]), "r"((a)[3]), "r"(b0), "r"(b1))

#define CP_ASYNC16(dst, src) \
    asm volatile("cp.async.cg.shared.global [%0], [%1], 16;" :: "r"(dst), "l"(src))
#define CP_COMMIT() asm volatile("cp.async.commit_group;" ::: "memory")
#define CP_WAIT0()  asm volatile("cp.async.wait_group 0;" ::: "memory")

// silu via tanh.approx: 1 MUFU + 2 FMA instead of 2 MUFU
__device__ __forceinline__ float silu_f(float x) {
    float t;
    asm("tanh.approx.f32 %0, %1;" : "=f"(t) : "f"(0.5f * x));
    return x * fmaf(0.5f, t, 0.5f);
}

__device__ __forceinline__ void red_add_v4(float* p, float a, float b, float c, float d) {
    asm volatile("red.global.add.v4.f32 [%0], {%1, %2, %3, %4};"
                 :: "l"(p), "f"(a), "f"(b), "f"(c), "f"(d) : "memory");
}

__device__ __forceinline__ uint32_t pk_h2(__half a, __half b) {
    __half2 t = __halves2half2(a, b);
    return *(uint32_t*)&t;
}

// ---------------- prep: B fragment images + zero agg ----------------
__global__ void prep_kernel(const float* __restrict__ mw1, const float* __restrict__ uw1,
                            const float* __restrict__ uw2) {
    if (blockIdx.x < 5) {
        const int which = blockIdx.x;
        const float* W;
        switch (which) {
            case 0: W = mw1; break;
            case 1: W = mw1 + DD * DD; break;
            case 2: W = uw1; break;
            case 3: W = uw1 + DD * DD; break;
            default: W = uw2; break;
        }
        unsigned* dst = &g_Bfrag[which][0];
        for (int e = threadIdx.x; e < 8192; e += blockDim.x) {
            int wn = e >> 11, c = (e >> 8) & 7, lane = (e >> 3) & 31, j = e & 7;
            int nf = j >> 1, h = j & 1;
            int n = wn * 32 + nf * 8 + (lane >> 2);
            int col = permcol(n);
            int k = c * 16 + h * 8 + (lane & 3) * 2;
            dst[e] = pk_h2(__float2half_rn(W[k * DD + col]),
                           __float2half_rn(W[(k + 1) * DD + col]));
        }
    } else {
        const int b = blockIdx.x - 5;
        float4* p = (float4*)g_agg;
        const int n4 = NNODES * DD / 4;
        for (int i = b * (int)blockDim.x + threadIdx.x; i < n4; i += 64 * (int)blockDim.x)
            p[i] = make_float4(0.f, 0.f, 0.f, 0.f);
    }
}

// ---------------- A tile convert: fp32 -> fp16 image ----------------
__device__ __forceinline__ void convertA(char* buf, const float* __restrict__ A,
                                         long rowbase) {
    const int r = threadIdx.x & 31;
    const int cseg = (threadIdx.x >> 5) << 5;
    const float4* srcp = (const float4*)(A + (rowbase + r) * DD + cseg);
#pragma unroll
    for (int j = 0; j < 4; j++) {
        float4 u = __ldg(srcp + 2 * j);
        float4 v = __ldg(srcp + 2 * j + 1);
        const int col0 = cseg + j * 8;
        const int c = col0 >> 4, h = (col0 >> 3) & 1;
        *(uint4*)(buf + img_offA(c, r, h)) = make_uint4(
            pk_h2(__float2half_rn(u.x), __float2half_rn(u.y)),
            pk_h2(__float2half_rn(u.z), __float2half_rn(u.w)),
            pk_h2(__float2half_rn(v.x), __float2half_rn(v.y)),
            pk_h2(__float2half_rn(v.z), __float2half_rn(v.w)));
    }
}

// ---------------- main GEMM kernel (P stage + edge stage) ----------------
template <bool BIAS, bool ADD, bool GATHER, bool SILU, bool SCATTER>
__global__ void __launch_bounds__(NTHREADS, 4)
tgemm(const float* __restrict__ A, const unsigned* __restrict__ Bf,
      const float* __restrict__ addv, const float* __restrict__ bias,
      const int* __restrict__ gsrc, const int* __restrict__ gdst,
      float* __restrict__ Out, int nrows) {
    extern __shared__ char sm[];
    __shared__ int s_dst[2][TILE_M];
    const uint32_t As = smem_u32(sm);
    const int tid = threadIdx.x, lane = tid & 31, wn = tid >> 5;
    const int srow = tid >> 2;
    const int qseg = (tid & 3) << 3;

    uint32_t bf[8][8];
    {
        const uint4* bp = (const uint4*)Bf;
#pragma unroll
        for (int c = 0; c < 8; c++) {
            const int base = ((wn * 8 + c) * 32 + lane) * 2;
            uint4 u0 = __ldg(bp + base);
            uint4 u1 = __ldg(bp + base + 1);
            bf[c][0] = u0.x; bf[c][1] = u0.y; bf[c][2] = u0.z; bf[c][3] = u0.w;
            bf[c][4] = u1.x; bf[c][5] = u1.y; bf[c][6] = u1.z; bf[c][7] = u1.w;
        }
    }
    float4 bias_r[2];
#pragma unroll
    for (int p = 0; p < 2; p++)
        bias_r[p] = BIAS
            ? __ldg((const float4*)(bias + wn * 32 + p * 16 + (lane & 3) * 4))
            : make_float4(0.f, 0.f, 0.f, 0.f);

    const int tiles = nrows / TILE_M;
    const int bid = blockIdx.x;
    if (bid >= tiles) return;
    const int ntb = (tiles - 1 - bid) / (int)gridDim.x + 1;

    convertA(sm, A, (long)bid * TILE_M);
    int idx_next = 0;
    if (GATHER) {
        int idx0 = __ldg(gsrc + (long)bid * TILE_M + srow);
        const float* gp = addv + (size_t)idx0 * DD;
        uint32_t sd = As + SM_STG + srow * 512;
#pragma unroll
        for (int i = 0; i < 8; i++) {
            int ch = qseg + i;
            CP_ASYNC16(sd + ((ch ^ (srow & 7)) << 4), gp + ch * 4);
        }
        CP_COMMIT();
        if (ntb > 1)
            idx_next = __ldg(gsrc + ((long)bid + gridDim.x) * TILE_M + srow);
    }
    if (SCATTER && tid >= TILE_M && tid < 2 * TILE_M)
        s_dst[0][tid - TILE_M] = __ldg(gdst + (long)bid * TILE_M + (tid - TILE_M));

    for (int it = 0; it < ntb; it++) {
        const long tile = (long)bid + (long)it * gridDim.x;
        const long rowbase = tile * TILE_M;
        const int pb = it & 1;
        if (GATHER) CP_WAIT0();
        __syncthreads();

        float acc[2][4][4];
#pragma unroll
        for (int mf = 0; mf < 2; mf++)
#pragma unroll
            for (int nf = 0; nf < 4; nf++)
#pragma unroll
                for (int q = 0; q < 4; q++) acc[mf][nf][q] = 0.f;

        const uint32_t Ab = As + pb * 8192;
#pragma unroll
        for (int c = 0; c < 8; c++) {
            uint32_t a[2][4];
            LDM4(a[0], ldm_addrA(Ab, c, 0, lane));
            LDM4(a[1], ldm_addrA(Ab, c, 1, lane));
#pragma unroll
            for (int mf = 0; mf < 2; mf++)
#pragma unroll
                for (int nf = 0; nf < 4; nf++)
                    MMA(acc[mf][nf], a[mf], bf[c][2 * nf], bf[c][2 * nf + 1]);
        }

        if (it + 1 < ntb) {
            const long nt = tile + gridDim.x;
            convertA(sm + (pb ^ 1) * 8192, A, nt * TILE_M);
            if (GATHER) {
                const float* gp = addv + (size_t)idx_next * DD;
                uint32_t sd = As + SM_STG + (pb ^ 1) * 16384 + srow * 512;
#pragma unroll
                for (int i = 0; i < 8; i++) {
                    int ch = qseg + i;
                    CP_ASYNC16(sd + ((ch ^ (srow & 7)) << 4), gp + ch * 4);
                }
                CP_COMMIT();
                if (it + 2 < ntb)
                    idx_next = __ldg(gsrc + (nt + gridDim.x) * TILE_M + srow);
            }
            if (SCATTER && tid >= TILE_M && tid < 2 * TILE_M)
                s_dst[pb ^ 1][tid - TILE_M] = __ldg(gdst + nt * TILE_M + (tid - TILE_M));
        }

        {
            const int q = lane & 3, ro = lane >> 2;
            const char* stg = sm + SM_STG + pb * 16384;
#pragma unroll
            for (int mf = 0; mf < 2; mf++) {
#pragma unroll
                for (int rh = 0; rh < 2; rh++) {
                    const int r = mf * 16 + rh * 8 + ro;
                    const long gr = rowbase + r;
                    const long orow = SCATTER ? (long)s_dst[pb][r] : gr;
#pragma unroll
                    for (int p = 0; p < 2; p++) {
                        const int cc = wn * 32 + p * 16 + q * 4;
                        float v0 = acc[mf][2 * p][2 * rh];
                        float v1 = acc[mf][2 * p][2 * rh + 1];
                        float v2 = acc[mf][2 * p + 1][2 * rh];
                        float v3 = acc[mf][2 * p + 1][2 * rh + 1];
                        if (ADD) {
                            float4 t;
                            if (GATHER) {
                                const int ch = wn * 8 + p * 4 + q;
                                t = *(const float4*)(stg + r * 512 +
                                                     ((ch ^ (r & 7)) << 4));
                            } else {
                                t = __ldg((const float4*)(addv + gr * DD + cc));
                            }
                            v0 += t.x; v1 += t.y; v2 += t.z; v3 += t.w;
                        }
                        if (BIAS) {
                            float4 b = bias_r[p];
                            v0 += b.x; v1 += b.y; v2 += b.z; v3 += b.w;
                        }
                        if (SILU) {
                            v0 = silu_f(v0); v1 = silu_f(v1);
                            v2 = silu_f(v2); v3 = silu_f(v3);
                        }
                        float* op = Out + orow * DD + cc;
                        if (SCATTER) red_add_v4(op, v0, v1, v2, v3);
                        else *(float4*)op = make_float4(v0, v1, v2, v3);
                    }
                }
            }
        }
    }
}

// ---------------- fused node-update kernel (stages 3+4+5) ----------------
// per tile: H = silu(nodes@uw1t + agg@uw1b + ub1); out = H@uw2 + nodes + ub2
__global__ void __launch_bounds__(NTHREADS, 2)
fusedk(const float* __restrict__ nodes, const float* __restrict__ agg,
       const unsigned* __restrict__ Bt, const unsigned* __restrict__ Bb,
       const unsigned* __restrict__ B2, const float* __restrict__ ub1,
       const float* __restrict__ ub2, float* __restrict__ Out) {
    extern __shared__ char sm[];          // A1/H 8K | A2 8K | B2 32K | B3 32K
    const uint32_t As = smem_u32(sm);
    const int tid = threadIdx.x, lane = tid & 31, wn = tid >> 5;
    const int q = lane & 3, ro = lane >> 2;

    // uw1_top panel -> registers
    uint32_t bf[8][8];
    {
        const uint4* bp = (const uint4*)Bt;
#pragma unroll
        for (int c = 0; c < 8; c++) {
            const int base = ((wn * 8 + c) * 32 + lane) * 2;
            uint4 u0 = __ldg(bp + base);
            uint4 u1 = __ldg(bp + base + 1);
            bf[c][0] = u0.x; bf[c][1] = u0.y; bf[c][2] = u0.z; bf[c][3] = u0.w;
            bf[c][4] = u1.x; bf[c][5] = u1.y; bf[c][6] = u1.z; bf[c][7] = u1.w;
        }
    }
    // uw1_bot and uw2 panels -> smem (same layout as global image)
    for (int i = tid; i < 2048; i += NTHREADS) {
        ((uint4*)(sm + FB2))[i] = __ldg((const uint4*)Bb + i);
        ((uint4*)(sm + FB3))[i] = __ldg((const uint4*)B2 + i);
    }
    float4 b1r[2], b2r[2];
#pragma unroll
    for (int p = 0; p < 2; p++) {
        b1r[p] = __ldg((const float4*)(ub1 + wn * 32 + p * 16 + q * 4));
        b2r[p] = __ldg((const float4*)(ub2 + wn * 32 + p * 16 + q * 4));
    }

    const int tiles = NNODES / TILE_M;
    for (int tile = blockIdx.x; tile < tiles; tile += (int)gridDim.x) {
        const long rowbase = (long)tile * TILE_M;
        convertA(sm, nodes, rowbase);
        convertA(sm + 8192, agg, rowbase);
        __syncthreads();

        float acc[2][4][4];
#pragma unroll
        for (int mf = 0; mf < 2; mf++)
#pragma unroll
            for (int nf = 0; nf < 4; nf++)
#pragma unroll
                for (int qq = 0; qq < 4; qq++) acc[mf][nf][qq] = 0.f;

        // pass1: nodes @ uw1_top (B regs)
#pragma unroll
        for (int c = 0; c < 8; c++) {
            uint32_t a[2][4];
            LDM4(a[0], ldm_addrA(As, c, 0, lane));
            LDM4(a[1], ldm_addrA(As, c, 1, lane));
#pragma unroll
            for (int mf = 0; mf < 2; mf++)
#pragma unroll
                for (int nf = 0; nf < 4; nf++)
                    MMA(acc[mf][nf], a[mf], bf[c][2 * nf], bf[c][2 * nf + 1]);
        }
        // pass2: agg @ uw1_bot (B from smem panel)
#pragma unroll
        for (int c = 0; c < 8; c++) {
            uint32_t a[2][4], b2f[8];
            LDM4(a[0], ldm_addrA(As + 8192, c, 0, lane));
            LDM4(a[1], ldm_addrA(As + 8192, c, 1, lane));
            {
                const uint4* p2 = (const uint4*)(sm + FB2 + ((wn * 8 + c) * 32 + lane) * 32);
                uint4 u0 = p2[0], u1 = p2[1];
                b2f[0]=u0.x; b2f[1]=u0.y; b2f[2]=u0.z; b2f[3]=u0.w;
                b2f[4]=u1.x; b2f[5]=u1.y; b2f[6]=u1.z; b2f[7]=u1.w;
            }
#pragma unroll
            for (int mf = 0; mf < 2; mf++)
#pragma unroll
                for (int nf = 0; nf < 4; nf++)
                    MMA(acc[mf][nf], a[mf], b2f[2 * nf], b2f[2 * nf + 1]);
        }
        __syncthreads();   // everyone done reading A1 image

        // H = silu(acc + ub1) -> fp16 image into A1 buffer (true-col order)
#pragma unroll
        for (int mf = 0; mf < 2; mf++) {
#pragma unroll
            for (int rh = 0; rh < 2; rh++) {
                const int r = mf * 16 + rh * 8 + ro;
#pragma unroll
                for (int p = 0; p < 2; p++) {
                    float4 b = b1r[p];
                    float v0 = silu_f(acc[mf][2 * p][2 * rh] + b.x);
                    float v1 = silu_f(acc[mf][2 * p][2 * rh + 1] + b.y);
                    float v2 = silu_f(acc[mf][2 * p + 1][2 * rh] + b.z);
                    float v3 = silu_f(acc[mf][2 * p + 1][2 * rh + 1] + b.w);
                    uint2 hv = make_uint2(pk_h2(__float2half_rn(v0), __float2half_rn(v1)),
                                          pk_h2(__float2half_rn(v2), __float2half_rn(v3)));
                    *(uint2*)(sm + img_offA(wn * 2 + p, r, q >> 1) + (q & 1) * 8) = hv;
                }
            }
        }
        __syncthreads();

        // pass3: H @ uw2 (B from smem panel); epilogue: + nodes + ub2 -> Out
#pragma unroll
        for (int mf = 0; mf < 2; mf++)
#pragma unroll
            for (int nf = 0; nf < 4; nf++)
#pragma unroll
                for (int qq = 0; qq < 4; qq++) acc[mf][nf][qq] = 0.f;
#pragma unroll
        for (int c = 0; c < 8; c++) {
            uint32_t a[2][4], b3f[8];
            LDM4(a[0], ldm_addrA(As, c, 0, lane));
            LDM4(a[1], ldm_addrA(As, c, 1, lane));
            {
                const uint4* p3 = (const uint4*)(sm + FB3 + ((wn * 8 + c) * 32 + lane) * 32);
                uint4 u0 = p3[0], u1 = p3[1];
                b3f[0]=u0.x; b3f[1]=u0.y; b3f[2]=u0.z; b3f[3]=u0.w;
                b3f[4]=u1.x; b3f[5]=u1.y; b3f[6]=u1.z; b3f[7]=u1.w;
            }
#pragma unroll
            for (int mf = 0; mf < 2; mf++)
#pragma unroll
                for (int nf = 0; nf < 4; nf++)
                    MMA(acc[mf][nf], a[mf], b3f[2 * nf], b3f[2 * nf + 1]);
        }
#pragma unroll
        for (int mf = 0; mf < 2; mf++) {
#pragma unroll
            for (int rh = 0; rh < 2; rh++) {
                const int r = mf * 16 + rh * 8 + ro;
                const long gr = rowbase + r;
#pragma unroll
                for (int p = 0; p < 2; p++) {
                    const int cc = wn * 32 + p * 16 + q * 4;
                    float4 t = __ldg((const float4*)(nodes + gr * DD + cc));
                    float4 b = b2r[p];
                    float v0 = acc[mf][2 * p][2 * rh] + t.x + b.x;
                    float v1 = acc[mf][2 * p][2 * rh + 1] + t.y + b.y;
                    float v2 = acc[mf][2 * p + 1][2 * rh] + t.z + b.z;
                    float v3 = acc[mf][2 * p + 1][2 * rh + 1] + t.w + b.w;
                    *(float4*)(Out + gr * DD + cc) = make_float4(v0, v1, v2, v3);
                }
            }
        }
        __syncthreads();
    }
}

// ---------------- launch ----------------
extern "C" void kernel_launch(void* const* d_in, const int* in_sizes, int n_in,
                              void* d_out, int out_size) {
    const float* nodes = (const float*)d_in[0];
    const int*   ei    = (const int*)d_in[1];   // [2,E]: row0=src, row1=dst
    const float* ef    = (const float*)d_in[2];
    const float* mw1   = (const float*)d_in[3];
    const float* mb1   = (const float*)d_in[4];
    const float* uw1   = (const float*)d_in[5];
    const float* ub1   = (const float*)d_in[6];
    const float* uw2   = (const float*)d_in[7];
    const float* ub2   = (const float*)d_in[8];
    float* out = (float*)d_out;

    unsigned* Bf;
    float *P, *agg;
    cudaGetSymbolAddress((void**)&Bf,  g_Bfrag);
    cudaGetSymbolAddress((void**)&P,   g_P);
    cudaGetSymbolAddress((void**)&agg, g_agg);

    cudaFuncSetAttribute(tgemm<false, true, true, true, true>,
                         cudaFuncAttributeMaxDynamicSharedMemorySize, SMEM_EDGE);
    cudaFuncSetAttribute(fusedk,
                         cudaFuncAttributeMaxDynamicSharedMemorySize, SMEM_FUSED);

    // 0) B fragment images + zero agg (one launch)
    prep_kernel<<<69, 256>>>(mw1, uw1, uw2);
    // 1) P = nodes @ mw1_top + mb1
    tgemm<true, false, false, false, false><<<NGRID, NTHREADS, SMEM_GEMM>>>(
        nodes, Bf + 0 * 8192, nullptr, mb1, nullptr, nullptr, P, NNODES);
    // 2) agg[dst] += silu(ef @ mw1_bot + P[src])
    tgemm<false, true, true, true, true><<<NGRID, NTHREADS, SMEM_EDGE>>>(
        ef, Bf + 1 * 8192, P, nullptr, ei, ei + NEDGES, agg, NEDGES);
    // 3) out = silu([nodes|agg] @ uw1 + ub1) @ uw2 + nodes + ub2  (fused)
    fusedk<<<NGRID, NTHREADS, SMEM_FUSED>>>(
        nodes, agg, Bf + 2 * 8192, Bf + 3 * 8192, Bf + 4 * 8192, ub1, ub2, out);
}

// round 10
// speedup vs baseline: 6.4376x; 1.3220x over previous
#include <cuda_runtime.h>
#include <cuda_fp16.h>
#include <cstdint>

#define DD       128
#define NNODES   40000
#define NEDGES   640000
#define NTHREADS 128
#define TILE_M   32
#define NGRID    592

// edge smem: [0,16K) A image x2, [16K,32K) fp16 gather staging x2
#define SM_STG     16384
#define SMEM_GEMM  16384
#define SMEM_EDGE  32768
// fused smem: [0,8K) A1/H image, [8K,16K) A2 image, [16K,48K) B2, [48K,80K) B3
#define FB2        16384
#define FB3        49152
#define SMEM_FUSED 81920

// ---------------- global scratch ----------------
__device__ __align__(16) unsigned g_Bfrag[5][8192];
__device__ __align__(16) __half g_Ph[(size_t)NNODES * DD];   // P in fp16
__device__ float g_agg[(size_t)NNODES * DD];

// ---------------- helpers ----------------
__host__ __device__ __forceinline__ int permcol(int n) {
    int nf = (n >> 3) & 3, j = n & 7;
    return (n & ~31) | ((nf >> 1) << 4) | ((j >> 1) << 2) | ((nf & 1) << 1) | (j & 1);
}
__device__ __forceinline__ int img_offA(int c, int r, int h) {
    int i = 2 * r + h;
    i ^= (i >> 3) & 1;
    return c * 1024 + (i << 4);
}
__device__ __forceinline__ uint32_t smem_u32(const void* p) {
    uint32_t a;
    asm("{ .reg .u64 t; cvta.to.shared.u64 t, %1; cvt.u32.u64 %0, t; }" : "=r"(a) : "l"(p));
    return a;
}
__device__ __forceinline__ uint32_t ldm_addrA(uint32_t base, int c, int mf, int lane) {
    int r = mf * 16 + ((lane >> 3) & 1) * 8 + (lane & 7);
    int h = lane >> 4;
    int i = 2 * r + h;
    i ^= (i >> 3) & 1;
    return base + c * 1024 + (i << 4);
}

#define LDM4(d, addr) \
    asm volatile("ldmatrix.sync.aligned.m8n8.x4.shared.b16 {%0,%1,%2,%3}, [%4];" \
                 : "=r"((d)[0]), "=r"((d)[1]), "=r"((d)[2]), "=r"((d)[3]) : "r"(addr))

#define MMA(d, a, b0, b1) \
    asm volatile("mma.sync.aligned.m16n8k16.row.col.f32.f16.f16.f32 " \
                 "{%0,%1,%2,%3}, {%4,%5,%6,%7}, {%8,%9}, {%0,%1,%2,%3};" \
                 : "+f"((d)[0]), "+f"((d)[1]), "+f"((d)[2]), "+f"((d)[3]) \
                 : "r"((a)[0]), "r"((a)[1]), "r"((a)[2]), "r"((a)[3]), "r"(b0), "r"(b1))

#define CP_ASYNC16(dst, src) \
    asm volatile("cp.async.cg.shared.global [%0], [%1], 16;" :: "r"(dst), "l"(src))
#define CP_COMMIT() asm volatile("cp.async.commit_group;" ::: "memory")
#define CP_WAIT0()  asm volatile("cp.async.wait_group 0;" ::: "memory")

// silu via tanh.approx: 1 MUFU + 2 FMA
__device__ __forceinline__ float silu_f(float x) {
    float t;
    asm("tanh.approx.f32 %0, %1;" : "=f"(t) : "f"(0.5f * x));
    return x * fmaf(0.5f, t, 0.5f);
}

__device__ __forceinline__ void red_add_v4(float* p, float a, float b, float c, float d) {
    asm volatile("red.global.add.v4.f32 [%0], {%1, %2, %3, %4};"
                 :: "l"(p), "f"(a), "f"(b), "f"(c), "f"(d) : "memory");
}

__device__ __forceinline__ uint32_t pk_h2(__half a, __half b) {
    __half2 t = __halves2half2(a, b);
    return *(uint32_t*)&t;
}

// ---------------- prep: B fragment images + zero agg ----------------
__global__ void prep_kernel(const float* __restrict__ mw1, const float* __restrict__ uw1,
                            const float* __restrict__ uw2) {
    if (blockIdx.x < 5) {
        const int which = blockIdx.x;
        const float* W;
        switch (which) {
            case 0: W = mw1; break;
            case 1: W = mw1 + DD * DD; break;
            case 2: W = uw1; break;
            case 3: W = uw1 + DD * DD; break;
            default: W = uw2; break;
        }
        unsigned* dst = &g_Bfrag[which][0];
        for (int e = threadIdx.x; e < 8192; e += blockDim.x) {
            int wn = e >> 11, c = (e >> 8) & 7, lane = (e >> 3) & 31, j = e & 7;
            int nf = j >> 1, h = j & 1;
            int n = wn * 32 + nf * 8 + (lane >> 2);
            int col = permcol(n);
            int k = c * 16 + h * 8 + (lane & 3) * 2;
            dst[e] = pk_h2(__float2half_rn(W[k * DD + col]),
                           __float2half_rn(W[(k + 1) * DD + col]));
        }
    } else {
        const int b = blockIdx.x - 5;
        float4* p = (float4*)g_agg;
        const int n4 = NNODES * DD / 4;
        for (int i = b * (int)blockDim.x + threadIdx.x; i < n4; i += 64 * (int)blockDim.x)
            p[i] = make_float4(0.f, 0.f, 0.f, 0.f);
    }
}

// ---------------- A tile convert: fp32 -> fp16 image ----------------
__device__ __forceinline__ void convertA(char* buf, const float* __restrict__ A,
                                         long rowbase) {
    const int r = threadIdx.x & 31;
    const int cseg = (threadIdx.x >> 5) << 5;
    const float4* srcp = (const float4*)(A + (rowbase + r) * DD + cseg);
#pragma unroll
    for (int j = 0; j < 4; j++) {
        float4 u = __ldg(srcp + 2 * j);
        float4 v = __ldg(srcp + 2 * j + 1);
        const int col0 = cseg + j * 8;
        const int c = col0 >> 4, h = (col0 >> 3) & 1;
        *(uint4*)(buf + img_offA(c, r, h)) = make_uint4(
            pk_h2(__float2half_rn(u.x), __float2half_rn(u.y)),
            pk_h2(__float2half_rn(u.z), __float2half_rn(u.w)),
            pk_h2(__float2half_rn(v.x), __float2half_rn(v.y)),
            pk_h2(__float2half_rn(v.z), __float2half_rn(v.w)));
    }
}

// ---------------- main GEMM kernel (P stage + edge stage) ----------------
// OUTH: write output as fp16 (P stage). GATHER: addv is fp16 (g_Ph), staged async.
template <bool BIAS, bool ADD, bool GATHER, bool SILU, bool SCATTER, bool OUTH>
__global__ void __launch_bounds__(NTHREADS, 4)
tgemm(const float* __restrict__ A, const unsigned* __restrict__ Bf,
      const void* __restrict__ addv, const float* __restrict__ bias,
      const int* __restrict__ gsrc, const int* __restrict__ gdst,
      void* __restrict__ Out, int nrows) {
    extern __shared__ char sm[];
    __shared__ int s_dst[2][TILE_M];
    const uint32_t As = smem_u32(sm);
    const int tid = threadIdx.x, lane = tid & 31, wn = tid >> 5;
    const int srow = tid >> 2;            // staged row
    const int qseg = (tid & 3) << 2;      // 16B-chunk base within 256B row: 0,4,8,12

    uint32_t bf[8][8];
    {
        const uint4* bp = (const uint4*)Bf;
#pragma unroll
        for (int c = 0; c < 8; c++) {
            const int base = ((wn * 8 + c) * 32 + lane) * 2;
            uint4 u0 = __ldg(bp + base);
            uint4 u1 = __ldg(bp + base + 1);
            bf[c][0] = u0.x; bf[c][1] = u0.y; bf[c][2] = u0.z; bf[c][3] = u0.w;
            bf[c][4] = u1.x; bf[c][5] = u1.y; bf[c][6] = u1.z; bf[c][7] = u1.w;
        }
    }
    float4 bias_r[2];
#pragma unroll
    for (int p = 0; p < 2; p++)
        bias_r[p] = BIAS
            ? __ldg((const float4*)(bias + wn * 32 + p * 16 + (lane & 3) * 4))
            : make_float4(0.f, 0.f, 0.f, 0.f);

    const int tiles = nrows / TILE_M;
    const int bid = blockIdx.x;
    if (bid >= tiles) return;
    const int ntb = (tiles - 1 - bid) / (int)gridDim.x + 1;

    convertA(sm, A, (long)bid * TILE_M);
    int idx_next = 0;
    if (GATHER) {
        int idx0 = __ldg(gsrc + (long)bid * TILE_M + srow);
        const __half* gp = (const __half*)addv + (size_t)idx0 * DD;
        uint32_t sd = As + SM_STG + srow * 256;
#pragma unroll
        for (int i = 0; i < 4; i++) {
            int ch = qseg + i;
            CP_ASYNC16(sd + ((ch ^ (srow & 7)) << 4), gp + ch * 8);
        }
        CP_COMMIT();
        if (ntb > 1)
            idx_next = __ldg(gsrc + ((long)bid + gridDim.x) * TILE_M + srow);
    }
    if (SCATTER && tid >= TILE_M && tid < 2 * TILE_M)
        s_dst[0][tid - TILE_M] = __ldg(gdst + (long)bid * TILE_M + (tid - TILE_M));

    for (int it = 0; it < ntb; it++) {
        const long tile = (long)bid + (long)it * gridDim.x;
        const long rowbase = tile * TILE_M;
        const int pb = it & 1;
        if (GATHER) CP_WAIT0();
        __syncthreads();

        float acc[2][4][4];
#pragma unroll
        for (int mf = 0; mf < 2; mf++)
#pragma unroll
            for (int nf = 0; nf < 4; nf++)
#pragma unroll
                for (int q = 0; q < 4; q++) acc[mf][nf][q] = 0.f;

        const uint32_t Ab = As + pb * 8192;
#pragma unroll
        for (int c = 0; c < 8; c++) {
            uint32_t a[2][4];
            LDM4(a[0], ldm_addrA(Ab, c, 0, lane));
            LDM4(a[1], ldm_addrA(Ab, c, 1, lane));
#pragma unroll
            for (int mf = 0; mf < 2; mf++)
#pragma unroll
                for (int nf = 0; nf < 4; nf++)
                    MMA(acc[mf][nf], a[mf], bf[c][2 * nf], bf[c][2 * nf + 1]);
        }

        if (it + 1 < ntb) {
            const long nt = tile + gridDim.x;
            convertA(sm + (pb ^ 1) * 8192, A, nt * TILE_M);
            if (GATHER) {
                const __half* gp = (const __half*)addv + (size_t)idx_next * DD;
                uint32_t sd = As + SM_STG + (pb ^ 1) * 8192 + srow * 256;
#pragma unroll
                for (int i = 0; i < 4; i++) {
                    int ch = qseg + i;
                    CP_ASYNC16(sd + ((ch ^ (srow & 7)) << 4), gp + ch * 8);
                }
                CP_COMMIT();
                if (it + 2 < ntb)
                    idx_next = __ldg(gsrc + (nt + gridDim.x) * TILE_M + srow);
            }
            if (SCATTER && tid >= TILE_M && tid < 2 * TILE_M)
                s_dst[pb ^ 1][tid - TILE_M] = __ldg(gdst + nt * TILE_M + (tid - TILE_M));
        }

        {
            const int q = lane & 3, ro = lane >> 2;
            const char* stg = sm + SM_STG + pb * 8192;
#pragma unroll
            for (int mf = 0; mf < 2; mf++) {
#pragma unroll
                for (int rh = 0; rh < 2; rh++) {
                    const int r = mf * 16 + rh * 8 + ro;
                    const long gr = rowbase + r;
                    const long orow = SCATTER ? (long)s_dst[pb][r] : gr;
#pragma unroll
                    for (int p = 0; p < 2; p++) {
                        const int cc = wn * 32 + p * 16 + q * 4;
                        float v0 = acc[mf][2 * p][2 * rh];
                        float v1 = acc[mf][2 * p][2 * rh + 1];
                        float v2 = acc[mf][2 * p + 1][2 * rh];
                        float v3 = acc[mf][2 * p + 1][2 * rh + 1];
                        if (ADD) {
                            if (GATHER) {
                                const int ch = wn * 4 + p * 2 + (q >> 1);
                                uint2 hv = *(const uint2*)(stg + r * 256 +
                                            ((ch ^ (r & 7)) << 4) + (q & 1) * 8);
                                float2 f0 = __half22float2(*(__half2*)&hv.x);
                                float2 f1 = __half22float2(*(__half2*)&hv.y);
                                v0 += f0.x; v1 += f0.y; v2 += f1.x; v3 += f1.y;
                            } else {
                                float4 t = __ldg((const float4*)((const float*)addv +
                                                                 gr * DD + cc));
                                v0 += t.x; v1 += t.y; v2 += t.z; v3 += t.w;
                            }
                        }
                        if (BIAS) {
                            float4 b = bias_r[p];
                            v0 += b.x; v1 += b.y; v2 += b.z; v3 += b.w;
                        }
                        if (SILU) {
                            v0 = silu_f(v0); v1 = silu_f(v1);
                            v2 = silu_f(v2); v3 = silu_f(v3);
                        }
                        if (OUTH) {
                            __half* oh = (__half*)Out + orow * DD + cc;
                            *(uint2*)oh = make_uint2(
                                pk_h2(__float2half_rn(v0), __float2half_rn(v1)),
                                pk_h2(__float2half_rn(v2), __float2half_rn(v3)));
                        } else {
                            float* op = (float*)Out + orow * DD + cc;
                            if (SCATTER) red_add_v4(op, v0, v1, v2, v3);
                            else *(float4*)op = make_float4(v0, v1, v2, v3);
                        }
                    }
                }
            }
        }
    }
}

// ---------------- fused node-update kernel (stages 3+4+5) ----------------
__global__ void __launch_bounds__(NTHREADS, 2)
fusedk(const float* __restrict__ nodes, const float* __restrict__ agg,
       const unsigned* __restrict__ Bt, const unsigned* __restrict__ Bb,
       const unsigned* __restrict__ B2, const float* __restrict__ ub1,
       const float* __restrict__ ub2, float* __restrict__ Out) {
    extern __shared__ char sm[];
    const uint32_t As = smem_u32(sm);
    const int tid = threadIdx.x, lane = tid & 31, wn = tid >> 5;
    const int q = lane & 3, ro = lane >> 2;

    uint32_t bf[8][8];
    {
        const uint4* bp = (const uint4*)Bt;
#pragma unroll
        for (int c = 0; c < 8; c++) {
            const int base = ((wn * 8 + c) * 32 + lane) * 2;
            uint4 u0 = __ldg(bp + base);
            uint4 u1 = __ldg(bp + base + 1);
            bf[c][0] = u0.x; bf[c][1] = u0.y; bf[c][2] = u0.z; bf[c][3] = u0.w;
            bf[c][4] = u1.x; bf[c][5] = u1.y; bf[c][6] = u1.z; bf[c][7] = u1.w;
        }
    }
    for (int i = tid; i < 2048; i += NTHREADS) {
        ((uint4*)(sm + FB2))[i] = __ldg((const uint4*)Bb + i);
        ((uint4*)(sm + FB3))[i] = __ldg((const uint4*)B2 + i);
    }
    float4 b1r[2], b2r[2];
#pragma unroll
    for (int p = 0; p < 2; p++) {
        b1r[p] = __ldg((const float4*)(ub1 + wn * 32 + p * 16 + q * 4));
        b2r[p] = __ldg((const float4*)(ub2 + wn * 32 + p * 16 + q * 4));
    }

    const int tiles = NNODES / TILE_M;
    for (int tile = blockIdx.x; tile < tiles; tile += (int)gridDim.x) {
        const long rowbase = (long)tile * TILE_M;
        convertA(sm, nodes, rowbase);
        convertA(sm + 8192, agg, rowbase);
        __syncthreads();

        float acc[2][4][4];
#pragma unroll
        for (int mf = 0; mf < 2; mf++)
#pragma unroll
            for (int nf = 0; nf < 4; nf++)
#pragma unroll
                for (int qq = 0; qq < 4; qq++) acc[mf][nf][qq] = 0.f;

#pragma unroll
        for (int c = 0; c < 8; c++) {
            uint32_t a[2][4];
            LDM4(a[0], ldm_addrA(As, c, 0, lane));
            LDM4(a[1], ldm_addrA(As, c, 1, lane));
#pragma unroll
            for (int mf = 0; mf < 2; mf++)
#pragma unroll
                for (int nf = 0; nf < 4; nf++)
                    MMA(acc[mf][nf], a[mf], bf[c][2 * nf], bf[c][2 * nf + 1]);
        }
#pragma unroll
        for (int c = 0; c < 8; c++) {
            uint32_t a[2][4], b2f[8];
            LDM4(a[0], ldm_addrA(As + 8192, c, 0, lane));
            LDM4(a[1], ldm_addrA(As + 8192, c, 1, lane));
            {
                const uint4* p2 = (const uint4*)(sm + FB2 + ((wn * 8 + c) * 32 + lane) * 32);
                uint4 u0 = p2[0], u1 = p2[1];
                b2f[0]=u0.x; b2f[1]=u0.y; b2f[2]=u0.z; b2f[3]=u0.w;
                b2f[4]=u1.x; b2f[5]=u1.y; b2f[6]=u1.z; b2f[7]=u1.w;
            }
#pragma unroll
            for (int mf = 0; mf < 2; mf++)
#pragma unroll
                for (int nf = 0; nf < 4; nf++)
                    MMA(acc[mf][nf], a[mf], b2f[2 * nf], b2f[2 * nf + 1]);
        }
        __syncthreads();

#pragma unroll
        for (int mf = 0; mf < 2; mf++) {
#pragma unroll
            for (int rh = 0; rh < 2; rh++) {
                const int r = mf * 16 + rh * 8 + ro;
#pragma unroll
                for (int p = 0; p < 2; p++) {
                    float4 b = b1r[p];
                    float v0 = silu_f(acc[mf][2 * p][2 * rh] + b.x);
                    float v1 = silu_f(acc[mf][2 * p][2 * rh + 1] + b.y);
                    float v2 = silu_f(acc[mf][2 * p + 1][2 * rh] + b.z);
                    float v3 = silu_f(acc[mf][2 * p + 1][2 * rh + 1] + b.w);
                    uint2 hv = make_uint2(pk_h2(__float2half_rn(v0), __float2half_rn(v1)),
                                          pk_h2(__float2half_rn(v2), __float2half_rn(v3)));
                    *(uint2*)(sm + img_offA(wn * 2 + p, r, q >> 1) + (q & 1) * 8) = hv;
                }
            }
        }
        __syncthreads();

#pragma unroll
        for (int mf = 0; mf < 2; mf++)
#pragma unroll
            for (int nf = 0; nf < 4; nf++)
#pragma unroll
                for (int qq = 0; qq < 4; qq++) acc[mf][nf][qq] = 0.f;
#pragma unroll
        for (int c = 0; c < 8; c++) {
            uint32_t a[2][4], b3f[8];
            LDM4(a[0], ldm_addrA(As, c, 0, lane));
            LDM4(a[1], ldm_addrA(As, c, 1, lane));
            {
                const uint4* p3 = (const uint4*)(sm + FB3 + ((wn * 8 + c) * 32 + lane) * 32);
                uint4 u0 = p3[0], u1 = p3[1];
                b3f[0]=u0.x; b3f[1]=u0.y; b3f[2]=u0.z; b3f[3]=u0.w;
                b3f[4]=u1.x; b3f[5]=u1.y; b3f[6]=u1.z; b3f[7]=u1.w;
            }
#pragma unroll
            for (int mf = 0; mf < 2; mf++)
#pragma unroll
                for (int nf = 0; nf < 4; nf++)
                    MMA(acc[mf][nf], a[mf], b3f[2 * nf], b3f[2 * nf + 1]);
        }
#pragma unroll
        for (int mf = 0; mf < 2; mf++) {
#pragma unroll
            for (int rh = 0; rh < 2; rh++) {
                const int r = mf * 16 + rh * 8 + ro;
                const long gr = rowbase + r;
#pragma unroll
                for (int p = 0; p < 2; p++) {
                    const int cc = wn * 32 + p * 16 + q * 4;
                    float4 t = __ldg((const float4*)(nodes + gr * DD + cc));
                    float4 b = b2r[p];
                    *(float4*)(Out + gr * DD + cc) = make_float4(
                        acc[mf][2 * p][2 * rh] + t.x + b.x,
                        acc[mf][2 * p][2 * rh + 1] + t.y + b.y,
                        acc[mf][2 * p + 1][2 * rh] + t.z + b.z,
                        acc[mf][2 * p + 1][2 * rh + 1] + t.w + b.w);
                }
            }
        }
        __syncthreads();
    }
}

// ---------------- launch ----------------
extern "C" void kernel_launch(void* const* d_in, const int* in_sizes, int n_in,
                              void* d_out, int out_size) {
    const float* nodes = (const float*)d_in[0];
    const int*   ei    = (const int*)d_in[1];
    const float* ef    = (const float*)d_in[2];
    const float* mw1   = (const float*)d_in[3];
    const float* mb1   = (const float*)d_in[4];
    const float* uw1   = (const float*)d_in[5];
    const float* ub1   = (const float*)d_in[6];
    const float* uw2   = (const float*)d_in[7];
    const float* ub2   = (const float*)d_in[8];
    float* out = (float*)d_out;

    unsigned* Bf;
    __half* Ph;
    float* agg;
    cudaGetSymbolAddress((void**)&Bf,  g_Bfrag);
    cudaGetSymbolAddress((void**)&Ph,  g_Ph);
    cudaGetSymbolAddress((void**)&agg, g_agg);

    cudaFuncSetAttribute(tgemm<false, true, true, true, true, false>,
                         cudaFuncAttributeMaxDynamicSharedMemorySize, SMEM_EDGE);
    cudaFuncSetAttribute(fusedk,
                         cudaFuncAttributeMaxDynamicSharedMemorySize, SMEM_FUSED);

    // 0) B fragment images + zero agg
    prep_kernel<<<69, 256>>>(mw1, uw1, uw2);
    // 1) Ph = fp16(nodes @ mw1_top + mb1)
    tgemm<true, false, false, false, false, true><<<NGRID, NTHREADS, SMEM_GEMM>>>(
        nodes, Bf + 0 * 8192, nullptr, mb1, nullptr, nullptr, Ph, NNODES);
    // 2) agg[dst] += silu(ef @ mw1_bot + Ph[src])
    tgemm<false, true, true, true, true, false><<<NGRID, NTHREADS, SMEM_EDGE>>>(
        ef, Bf + 1 * 8192, Ph, nullptr, ei, ei + NEDGES, agg, NEDGES);
    // 3) out = silu([nodes|agg] @ uw1 + ub1) @ uw2 + nodes + ub2  (fused)
    fusedk<<<NGRID, NTHREADS, SMEM_FUSED>>>(
        nodes, agg, Bf + 2 * 8192, Bf + 3 * 8192, Bf + 4 * 8192, ub1, ub2, out);
}

// round 11
// speedup vs baseline: 7.0914x; 1.1015x over previous
#include <cuda_runtime.h>
#include <cuda_fp16.h>
#include <cstdint>

#define DD       128
#define NNODES   40000
#define NEDGES   640000
#define NTHREADS 128
#define TILE_M   32
#define NGRID    592

// edge smem: [0,16K) A image x2, [16K,32K) fp16 gather staging x2
#define SM_STG     16384
#define SMEM_GEMM  16384
#define SMEM_EDGE  32768
// fused smem: [0,8K) A1/H image, [8K,16K) A2 image
#define SMEM_FUSED 16384

// ---------------- global scratch ----------------
__device__ __align__(16) unsigned g_Bfrag[5][8192];
__device__ __align__(16) __half g_Ph[(size_t)NNODES * DD];    // P in fp16
__device__ __align__(16) __half g_aggh[(size_t)NNODES * DD];  // agg in fp16

// ---------------- helpers ----------------
__host__ __device__ __forceinline__ int permcol(int n) {
    int nf = (n >> 3) & 3, j = n & 7;
    return (n & ~31) | ((nf >> 1) << 4) | ((j >> 1) << 2) | ((nf & 1) << 1) | (j & 1);
}
__device__ __forceinline__ int img_offA(int c, int r, int h) {
    int i = 2 * r + h;
    i ^= (i >> 3) & 1;
    return c * 1024 + (i << 4);
}
__device__ __forceinline__ uint32_t smem_u32(const void* p) {
    uint32_t a;
    asm("{ .reg .u64 t; cvta.to.shared.u64 t, %1; cvt.u32.u64 %0, t; }" : "=r"(a) : "l"(p));
    return a;
}
__device__ __forceinline__ uint32_t ldm_addrA(uint32_t base, int c, int mf, int lane) {
    int r = mf * 16 + ((lane >> 3) & 1) * 8 + (lane & 7);
    int h = lane >> 4;
    int i = 2 * r + h;
    i ^= (i >> 3) & 1;
    return base + c * 1024 + (i << 4);
}

#define LDM4(d, addr) \
    asm volatile("ldmatrix.sync.aligned.m8n8.x4.shared.b16 {%0,%1,%2,%3}, [%4];" \
                 : "=r"((d)[0]), "=r"((d)[1]), "=r"((d)[2]), "=r"((d)[3]) : "r"(addr))

#define MMA(d, a, b0, b1) \
    asm volatile("mma.sync.aligned.m16n8k16.row.col.f32.f16.f16.f32 " \
                 "{%0,%1,%2,%3}, {%4,%5,%6,%7}, {%8,%9}, {%0,%1,%2,%3};" \
                 : "+f"((d)[0]), "+f"((d)[1]), "+f"((d)[2]), "+f"((d)[3]) \
                 : "r"((a)[0]), "r"((a)[1]), "r"((a)[2]), "r"((a)[3]), "r"(b0), "r"(b1))

#define CP_ASYNC16(dst, src) \
    asm volatile("cp.async.cg.shared.global [%0], [%1], 16;" :: "r"(dst), "l"(src))
#define CP_COMMIT() asm volatile("cp.async.commit_group;" ::: "memory")
#define CP_WAIT0()  asm volatile("cp.async.wait_group 0;" ::: "memory")

// silu via tanh.approx: 1 MUFU + 2 FMA
__device__ __forceinline__ float silu_f(float x) {
    float t;
    asm("tanh.approx.f32 %0, %1;" : "=f"(t) : "f"(0.5f * x));
    return x * fmaf(0.5f, t, 0.5f);
}

__device__ __forceinline__ uint32_t pk_h2(__half a, __half b) {
    __half2 t = __halves2half2(a, b);
    return *(uint32_t*)&t;
}

// fp16 vector reduction: adds 4 halves (2 x f16x2) at p
__device__ __forceinline__ void red_add_h4(__half* p, float v0, float v1,
                                           float v2, float v3) {
    uint32_t h0 = pk_h2(__float2half_rn(v0), __float2half_rn(v1));
    uint32_t h1 = pk_h2(__float2half_rn(v2), __float2half_rn(v3));
    asm volatile("red.global.add.noftz.v2.f16x2 [%0], {%1, %2};"
                 :: "l"(p), "r"(h0), "r"(h1) : "memory");
}

// ---------------- prep: B fragment images + zero agg ----------------
__global__ void prep_kernel(const float* __restrict__ mw1, const float* __restrict__ uw1,
                            const float* __restrict__ uw2) {
    if (blockIdx.x < 5) {
        const int which = blockIdx.x;
        const float* W;
        switch (which) {
            case 0: W = mw1; break;
            case 1: W = mw1 + DD * DD; break;
            case 2: W = uw1; break;
            case 3: W = uw1 + DD * DD; break;
            default: W = uw2; break;
        }
        unsigned* dst = &g_Bfrag[which][0];
        for (int e = threadIdx.x; e < 8192; e += blockDim.x) {
            int wn = e >> 11, c = (e >> 8) & 7, lane = (e >> 3) & 31, j = e & 7;
            int nf = j >> 1, h = j & 1;
            int n = wn * 32 + nf * 8 + (lane >> 2);
            int col = permcol(n);
            int k = c * 16 + h * 8 + (lane & 3) * 2;
            dst[e] = pk_h2(__float2half_rn(W[k * DD + col]),
                           __float2half_rn(W[(k + 1) * DD + col]));
        }
    } else {
        const int b = blockIdx.x - 5;
        uint4* p = (uint4*)g_aggh;
        const int n16 = NNODES * DD / 8;    // 16B chunks of fp16 buffer
        for (int i = b * (int)blockDim.x + threadIdx.x; i < n16; i += 64 * (int)blockDim.x)
            p[i] = make_uint4(0u, 0u, 0u, 0u);
    }
}

// ---------------- A tile converts ----------------
// fp32 source -> fp16 image
__device__ __forceinline__ void convertA(char* buf, const float* __restrict__ A,
                                         long rowbase) {
    const int r = threadIdx.x & 31;
    const int cseg = (threadIdx.x >> 5) << 5;
    const float4* srcp = (const float4*)(A + (rowbase + r) * DD + cseg);
#pragma unroll
    for (int j = 0; j < 4; j++) {
        float4 u = __ldg(srcp + 2 * j);
        float4 v = __ldg(srcp + 2 * j + 1);
        const int col0 = cseg + j * 8;
        const int c = col0 >> 4, h = (col0 >> 3) & 1;
        *(uint4*)(buf + img_offA(c, r, h)) = make_uint4(
            pk_h2(__float2half_rn(u.x), __float2half_rn(u.y)),
            pk_h2(__float2half_rn(u.z), __float2half_rn(u.w)),
            pk_h2(__float2half_rn(v.x), __float2half_rn(v.y)),
            pk_h2(__float2half_rn(v.z), __float2half_rn(v.w)));
    }
}
// fp16 source -> image (bit copy)
__device__ __forceinline__ void convertAh(char* buf, const __half* __restrict__ A,
                                          long rowbase) {
    const int r = threadIdx.x & 31;
    const int cseg = (threadIdx.x >> 5) << 5;
    const uint4* srcp = (const uint4*)(A + (rowbase + r) * DD + cseg);
#pragma unroll
    for (int j = 0; j < 4; j++) {
        uint4 u = __ldg(srcp + j);
        const int col0 = cseg + j * 8;
        const int c = col0 >> 4, h = (col0 >> 3) & 1;
        *(uint4*)(buf + img_offA(c, r, h)) = u;
    }
}

// load one B chunk (8 u32 frags) from a gmem fragment image (L2-hit)
__device__ __forceinline__ void ldB(uint32_t* b8, const unsigned* __restrict__ Bsrc,
                                    int wn, int c, int lane) {
    const uint4* bp = (const uint4*)Bsrc + ((wn * 8 + c) * 32 + lane) * 2;
    uint4 u0 = __ldg(bp);
    uint4 u1 = __ldg(bp + 1);
    b8[0] = u0.x; b8[1] = u0.y; b8[2] = u0.z; b8[3] = u0.w;
    b8[4] = u1.x; b8[5] = u1.y; b8[6] = u1.z; b8[7] = u1.w;
}

// ---------------- main GEMM kernel (P stage + edge stage) ----------------
// OUTH: write fp16 output (P stage). GATHER: addv fp16 staged async.
// SCATTER: fp16 vector red into Out (agg).
template <bool BIAS, bool ADD, bool GATHER, bool SILU, bool SCATTER, bool OUTH>
__global__ void __launch_bounds__(NTHREADS, 4)
tgemm(const float* __restrict__ A, const unsigned* __restrict__ Bf,
      const void* __restrict__ addv, const float* __restrict__ bias,
      const int* __restrict__ gsrc, const int* __restrict__ gdst,
      void* __restrict__ Out, int nrows) {
    extern __shared__ char sm[];
    __shared__ int s_dst[2][TILE_M];
    const uint32_t As = smem_u32(sm);
    const int tid = threadIdx.x, lane = tid & 31, wn = tid >> 5;
    const int srow = tid >> 2;
    const int qseg = (tid & 3) << 2;

    uint32_t bf[8][8];
#pragma unroll
    for (int c = 0; c < 8; c++) ldB(bf[c], Bf, wn, c, lane);

    float4 bias_r[2];
#pragma unroll
    for (int p = 0; p < 2; p++)
        bias_r[p] = BIAS
            ? __ldg((const float4*)(bias + wn * 32 + p * 16 + (lane & 3) * 4))
            : make_float4(0.f, 0.f, 0.f, 0.f);

    const int tiles = nrows / TILE_M;
    const int bid = blockIdx.x;
    if (bid >= tiles) return;
    const int ntb = (tiles - 1 - bid) / (int)gridDim.x + 1;

    convertA(sm, A, (long)bid * TILE_M);
    int idx_next = 0;
    if (GATHER) {
        int idx0 = __ldg(gsrc + (long)bid * TILE_M + srow);
        const __half* gp = (const __half*)addv + (size_t)idx0 * DD;
        uint32_t sd = As + SM_STG + srow * 256;
#pragma unroll
        for (int i = 0; i < 4; i++) {
            int ch = qseg + i;
            CP_ASYNC16(sd + ((ch ^ (srow & 7)) << 4), gp + ch * 8);
        }
        CP_COMMIT();
        if (ntb > 1)
            idx_next = __ldg(gsrc + ((long)bid + gridDim.x) * TILE_M + srow);
    }
    if (SCATTER && tid >= TILE_M && tid < 2 * TILE_M)
        s_dst[0][tid - TILE_M] = __ldg(gdst + (long)bid * TILE_M + (tid - TILE_M));

    for (int it = 0; it < ntb; it++) {
        const long tile = (long)bid + (long)it * gridDim.x;
        const long rowbase = tile * TILE_M;
        const int pb = it & 1;
        if (GATHER) CP_WAIT0();
        __syncthreads();

        float acc[2][4][4];
#pragma unroll
        for (int mf = 0; mf < 2; mf++)
#pragma unroll
            for (int nf = 0; nf < 4; nf++)
#pragma unroll
                for (int q = 0; q < 4; q++) acc[mf][nf][q] = 0.f;

        const uint32_t Ab = As + pb * 8192;
#pragma unroll
        for (int c = 0; c < 8; c++) {
            uint32_t a[2][4];
            LDM4(a[0], ldm_addrA(Ab, c, 0, lane));
            LDM4(a[1], ldm_addrA(Ab, c, 1, lane));
#pragma unroll
            for (int mf = 0; mf < 2; mf++)
#pragma unroll
                for (int nf = 0; nf < 4; nf++)
                    MMA(acc[mf][nf], a[mf], bf[c][2 * nf], bf[c][2 * nf + 1]);
        }

        if (it + 1 < ntb) {
            const long nt = tile + gridDim.x;
            convertA(sm + (pb ^ 1) * 8192, A, nt * TILE_M);
            if (GATHER) {
                const __half* gp = (const __half*)addv + (size_t)idx_next * DD;
                uint32_t sd = As + SM_STG + (pb ^ 1) * 8192 + srow * 256;
#pragma unroll
                for (int i = 0; i < 4; i++) {
                    int ch = qseg + i;
                    CP_ASYNC16(sd + ((ch ^ (srow & 7)) << 4), gp + ch * 8);
                }
                CP_COMMIT();
                if (it + 2 < ntb)
                    idx_next = __ldg(gsrc + (nt + gridDim.x) * TILE_M + srow);
            }
            if (SCATTER && tid >= TILE_M && tid < 2 * TILE_M)
                s_dst[pb ^ 1][tid - TILE_M] = __ldg(gdst + nt * TILE_M + (tid - TILE_M));
        }

        {
            const int q = lane & 3, ro = lane >> 2;
            const char* stg = sm + SM_STG + pb * 8192;
#pragma unroll
            for (int mf = 0; mf < 2; mf++) {
#pragma unroll
                for (int rh = 0; rh < 2; rh++) {
                    const int r = mf * 16 + rh * 8 + ro;
                    const long gr = rowbase + r;
                    const long orow = SCATTER ? (long)s_dst[pb][r] : gr;
#pragma unroll
                    for (int p = 0; p < 2; p++) {
                        const int cc = wn * 32 + p * 16 + q * 4;
                        float v0 = acc[mf][2 * p][2 * rh];
                        float v1 = acc[mf][2 * p][2 * rh + 1];
                        float v2 = acc[mf][2 * p + 1][2 * rh];
                        float v3 = acc[mf][2 * p + 1][2 * rh + 1];
                        if (ADD) {
                            if (GATHER) {
                                const int ch = wn * 4 + p * 2 + (q >> 1);
                                uint2 hv = *(const uint2*)(stg + r * 256 +
                                            ((ch ^ (r & 7)) << 4) + (q & 1) * 8);
                                float2 f0 = __half22float2(*(__half2*)&hv.x);
                                float2 f1 = __half22float2(*(__half2*)&hv.y);
                                v0 += f0.x; v1 += f0.y; v2 += f1.x; v3 += f1.y;
                            } else {
                                float4 t = __ldg((const float4*)((const float*)addv +
                                                                 gr * DD + cc));
                                v0 += t.x; v1 += t.y; v2 += t.z; v3 += t.w;
                            }
                        }
                        if (BIAS) {
                            float4 b = bias_r[p];
                            v0 += b.x; v1 += b.y; v2 += b.z; v3 += b.w;
                        }
                        if (SILU) {
                            v0 = silu_f(v0); v1 = silu_f(v1);
                            v2 = silu_f(v2); v3 = silu_f(v3);
                        }
                        if (OUTH) {
                            __half* oh = (__half*)Out + orow * DD + cc;
                            *(uint2*)oh = make_uint2(
                                pk_h2(__float2half_rn(v0), __float2half_rn(v1)),
                                pk_h2(__float2half_rn(v2), __float2half_rn(v3)));
                        } else if (SCATTER) {
                            red_add_h4((__half*)Out + orow * DD + cc, v0, v1, v2, v3);
                        } else {
                            *(float4*)((float*)Out + orow * DD + cc) =
                                make_float4(v0, v1, v2, v3);
                        }
                    }
                }
            }
        }
    }
}

// ---------------- fused node-update kernel (stages 3+4+5) ----------------
// All B panels from gmem (L2-resident); smem only A/H images -> 3 CTAs/SM.
__global__ void __launch_bounds__(NTHREADS, 3)
fusedk(const float* __restrict__ nodes, const __half* __restrict__ aggh,
       const unsigned* __restrict__ Bt, const unsigned* __restrict__ Bb,
       const unsigned* __restrict__ B2, const float* __restrict__ ub1,
       const float* __restrict__ ub2, float* __restrict__ Out) {
    extern __shared__ char sm[];          // A1/H 8K | A2 8K
    const uint32_t As = smem_u32(sm);
    const int tid = threadIdx.x, lane = tid & 31, wn = tid >> 5;
    const int q = lane & 3, ro = lane >> 2;

    float4 b1r[2], b2r[2];
#pragma unroll
    for (int p = 0; p < 2; p++) {
        b1r[p] = __ldg((const float4*)(ub1 + wn * 32 + p * 16 + q * 4));
        b2r[p] = __ldg((const float4*)(ub2 + wn * 32 + p * 16 + q * 4));
    }

    const int tiles = NNODES / TILE_M;
    for (int tile = blockIdx.x; tile < tiles; tile += (int)gridDim.x) {
        const long rowbase = (long)tile * TILE_M;
        convertA(sm, nodes, rowbase);
        convertAh(sm + 8192, aggh, rowbase);
        __syncthreads();

        float acc[2][4][4];
#pragma unroll
        for (int mf = 0; mf < 2; mf++)
#pragma unroll
            for (int nf = 0; nf < 4; nf++)
#pragma unroll
                for (int qq = 0; qq < 4; qq++) acc[mf][nf][qq] = 0.f;

        // pass1: nodes @ uw1_top ; pass2: agg @ uw1_bot
#pragma unroll
        for (int c = 0; c < 8; c++) {
            uint32_t a[2][4], bfr[8];
            ldB(bfr, Bt, wn, c, lane);
            LDM4(a[0], ldm_addrA(As, c, 0, lane));
            LDM4(a[1], ldm_addrA(As, c, 1, lane));
#pragma unroll
            for (int mf = 0; mf < 2; mf++)
#pragma unroll
                for (int nf = 0; nf < 4; nf++)
                    MMA(acc[mf][nf], a[mf], bfr[2 * nf], bfr[2 * nf + 1]);
        }
#pragma unroll
        for (int c = 0; c < 8; c++) {
            uint32_t a[2][4], bfr[8];
            ldB(bfr, Bb, wn, c, lane);
            LDM4(a[0], ldm_addrA(As + 8192, c, 0, lane));
            LDM4(a[1], ldm_addrA(As + 8192, c, 1, lane));
#pragma unroll
            for (int mf = 0; mf < 2; mf++)
#pragma unroll
                for (int nf = 0; nf < 4; nf++)
                    MMA(acc[mf][nf], a[mf], bfr[2 * nf], bfr[2 * nf + 1]);
        }
        __syncthreads();

        // H = silu(acc + ub1) -> fp16 image into A1 buffer
#pragma unroll
        for (int mf = 0; mf < 2; mf++) {
#pragma unroll
            for (int rh = 0; rh < 2; rh++) {
                const int r = mf * 16 + rh * 8 + ro;
#pragma unroll
                for (int p = 0; p < 2; p++) {
                    float4 b = b1r[p];
                    float v0 = silu_f(acc[mf][2 * p][2 * rh] + b.x);
                    float v1 = silu_f(acc[mf][2 * p][2 * rh + 1] + b.y);
                    float v2 = silu_f(acc[mf][2 * p + 1][2 * rh] + b.z);
                    float v3 = silu_f(acc[mf][2 * p + 1][2 * rh + 1] + b.w);
                    uint2 hv = make_uint2(pk_h2(__float2half_rn(v0), __float2half_rn(v1)),
                                          pk_h2(__float2half_rn(v2), __float2half_rn(v3)));
                    *(uint2*)(sm + img_offA(wn * 2 + p, r, q >> 1) + (q & 1) * 8) = hv;
                }
            }
        }
        __syncthreads();

        // pass3: H @ uw2 ; epilogue: + nodes + ub2 -> Out
#pragma unroll
        for (int mf = 0; mf < 2; mf++)
#pragma unroll
            for (int nf = 0; nf < 4; nf++)
#pragma unroll
                for (int qq = 0; qq < 4; qq++) acc[mf][nf][qq] = 0.f;
#pragma unroll
        for (int c = 0; c < 8; c++) {
            uint32_t a[2][4], bfr[8];
            ldB(bfr, B2, wn, c, lane);
            LDM4(a[0], ldm_addrA(As, c, 0, lane));
            LDM4(a[1], ldm_addrA(As, c, 1, lane));
#pragma unroll
            for (int mf = 0; mf < 2; mf++)
#pragma unroll
                for (int nf = 0; nf < 4; nf++)
                    MMA(acc[mf][nf], a[mf], bfr[2 * nf], bfr[2 * nf + 1]);
        }
#pragma unroll
        for (int mf = 0; mf < 2; mf++) {
#pragma unroll
            for (int rh = 0; rh < 2; rh++) {
                const int r = mf * 16 + rh * 8 + ro;
                const long gr = rowbase + r;
#pragma unroll
                for (int p = 0; p < 2; p++) {
                    const int cc = wn * 32 + p * 16 + q * 4;
                    float4 t = __ldg((const float4*)(nodes + gr * DD + cc));
                    float4 b = b2r[p];
                    *(float4*)(Out + gr * DD + cc) = make_float4(
                        acc[mf][2 * p][2 * rh] + t.x + b.x,
                        acc[mf][2 * p][2 * rh + 1] + t.y + b.y,
                        acc[mf][2 * p + 1][2 * rh] + t.z + b.z,
                        acc[mf][2 * p + 1][2 * rh + 1] + t.w + b.w);
                }
            }
        }
        __syncthreads();
    }
}

// ---------------- launch ----------------
extern "C" void kernel_launch(void* const* d_in, const int* in_sizes, int n_in,
                              void* d_out, int out_size) {
    const float* nodes = (const float*)d_in[0];
    const int*   ei    = (const int*)d_in[1];
    const float* ef    = (const float*)d_in[2];
    const float* mw1   = (const float*)d_in[3];
    const float* mb1   = (const float*)d_in[4];
    const float* uw1   = (const float*)d_in[5];
    const float* ub1   = (const float*)d_in[6];
    const float* uw2   = (const float*)d_in[7];
    const float* ub2   = (const float*)d_in[8];
    float* out = (float*)d_out;

    unsigned* Bf;
    __half *Ph, *aggh;
    cudaGetSymbolAddress((void**)&Bf,   g_Bfrag);
    cudaGetSymbolAddress((void**)&Ph,   g_Ph);
    cudaGetSymbolAddress((void**)&aggh, g_aggh);

    cudaFuncSetAttribute(tgemm<false, true, true, true, true, false>,
                         cudaFuncAttributeMaxDynamicSharedMemorySize, SMEM_EDGE);

    // 0) B fragment images + zero agg
    prep_kernel<<<69, 256>>>(mw1, uw1, uw2);
    // 1) Ph = fp16(nodes @ mw1_top + mb1)
    tgemm<true, false, false, false, false, true><<<NGRID, NTHREADS, SMEM_GEMM>>>(
        nodes, Bf + 0 * 8192, nullptr, mb1, nullptr, nullptr, Ph, NNODES);
    // 2) aggh[dst] += fp16(silu(ef @ mw1_bot + Ph[src]))
    tgemm<false, true, true, true, true, false><<<NGRID, NTHREADS, SMEM_EDGE>>>(
        ef, Bf + 1 * 8192, Ph, nullptr, ei, ei + NEDGES, aggh, NEDGES);
    // 3) out = silu([nodes|aggh] @ uw1 + ub1) @ uw2 + nodes + ub2  (fused)
    fusedk<<<NGRID, NTHREADS, SMEM_FUSED>>>(
        nodes, aggh, Bf + 2 * 8192, Bf + 3 * 8192, Bf + 4 * 8192, ub1, ub2, out);
}